// round 1
// baseline (speedup 1.0000x reference)
#include <cuda_runtime.h>
#include <math.h>

#define L    384
#define DP   128
#define NH   4
#define DH   32
#define LL   (L*L)            // 147456

// ---------------- scratch (static device allocations; no cudaMalloc) ----------------
__device__ float g_pn[LL*DP];      // LN(pair_t)  row p = n*L + i
__device__ float g_q [LL*DP];      // pn @ Wq * 1/sqrt(d)
__device__ float g_k [LL*DP];      // pn @ Wk / L
__device__ float g_v [LL*DP];      // pn @ Wv
__device__ float g_gate[LL*DP];    // sigmoid(pn @ Wg + bg)
__device__ float g_o [LL*DP];      // attention output (pre-gate)
__device__ float g_attn [NH*LL];   // [h][i][j] logits, then softmax in-place
__device__ float g_battn[LL*NH];   // [(i*L+j)*4 + h] learned bias term

// ---------------- kernel 1: layernorm of transposed pair ----------------
// pn[n*L+i][c] = LN_c(pair[i*L+n][c]) * gamma + beta.  one warp per row.
__global__ __launch_bounds__(256) void k_ln_pair(const float* __restrict__ pair,
                                                 const float* __restrict__ gamma,
                                                 const float* __restrict__ beta)
{
    int warp = (blockIdx.x * blockDim.x + threadIdx.x) >> 5;
    int lane = threadIdx.x & 31;
    if (warp >= LL) return;
    int n = warp / L, i = warp % L;
    const float4* src = (const float4*)(pair + (size_t)(i*L + n) * DP);
    float4 x = src[lane];
    float s  = x.x + x.y + x.z + x.w;
    float ss = x.x*x.x + x.y*x.y + x.z*x.z + x.w*x.w;
    #pragma unroll
    for (int o = 16; o; o >>= 1) {
        s  += __shfl_xor_sync(0xffffffffu, s,  o);
        ss += __shfl_xor_sync(0xffffffffu, ss, o);
    }
    float mean = s * (1.0f/DP);
    float var  = ss * (1.0f/DP) - mean*mean;
    float inv  = rsqrtf(var + 1e-5f);
    float4 g = ((const float4*)gamma)[lane];
    float4 b = ((const float4*)beta )[lane];
    float4 y;
    y.x = (x.x - mean)*inv*g.x + b.x;
    y.y = (x.y - mean)*inv*g.y + b.y;
    y.z = (x.z - mean)*inv*g.z + b.z;
    y.w = (x.w - mean)*inv*g.w + b.w;
    ((float4*)(g_pn + (size_t)warp * DP))[lane] = y;
}

// ---------------- kernel 2: bias path: LN(bias_t[i,j,:]) @ Wb -> [i,j,h] ----------------
// bias_t[i,j,c] = bias[j*L+i][c].  one warp per (i,j).
__global__ __launch_bounds__(256) void k_bias(const float* __restrict__ bias,
                                              const float* __restrict__ gamma,
                                              const float* __restrict__ beta,
                                              const float* __restrict__ Wb)
{
    int warp = (blockIdx.x * blockDim.x + threadIdx.x) >> 5;
    int lane = threadIdx.x & 31;
    if (warp >= LL) return;
    int i = warp / L, j = warp % L;
    const float4* src = (const float4*)(bias + (size_t)(j*L + i) * DP);
    float4 x = src[lane];
    float s  = x.x + x.y + x.z + x.w;
    float ss = x.x*x.x + x.y*x.y + x.z*x.z + x.w*x.w;
    #pragma unroll
    for (int o = 16; o; o >>= 1) {
        s  += __shfl_xor_sync(0xffffffffu, s,  o);
        ss += __shfl_xor_sync(0xffffffffu, ss, o);
    }
    float mean = s * (1.0f/DP);
    float var  = ss * (1.0f/DP) - mean*mean;
    float inv  = rsqrtf(var + 1e-5f);
    float4 g = ((const float4*)gamma)[lane];
    float4 b = ((const float4*)beta )[lane];
    float y[4];
    y[0] = (x.x - mean)*inv*g.x + b.x;
    y[1] = (x.y - mean)*inv*g.y + b.y;
    y[2] = (x.z - mean)*inv*g.z + b.z;
    y[3] = (x.w - mean)*inv*g.w + b.w;
    float acc[NH] = {0.f, 0.f, 0.f, 0.f};
    #pragma unroll
    for (int t = 0; t < 4; t++) {
        int c = lane*4 + t;
        #pragma unroll
        for (int h = 0; h < NH; h++)
            acc[h] += y[t] * Wb[c*NH + h];
    }
    #pragma unroll
    for (int h = 0; h < NH; h++)
        #pragma unroll
        for (int o = 16; o; o >>= 1)
            acc[h] += __shfl_xor_sync(0xffffffffu, acc[h], o);
    if (lane == 0) {
        float4* dst = (float4*)(g_battn + (size_t)warp * NH);
        *dst = make_float4(acc[0], acc[1], acc[2], acc[3]);
    }
}

// ---------------- kernel 3: projections GEMM ----------------
// g_pn [LL,128] @ W [128,128] -> q/k/v/gate, one matrix per blockIdx.y.
#define BM 128
#define BN 128
#define BK 32
__global__ __launch_bounds__(256) void k_proj(const float* __restrict__ Wq,
                                              const float* __restrict__ Wk,
                                              const float* __restrict__ Wv,
                                              const float* __restrict__ Wg,
                                              const float* __restrict__ bg)
{
    __shared__ float As[BK][BM+4];   // [k][m], padded
    __shared__ float Bs[BK][BN];     // [k][n]
    int which = blockIdx.y;
    const float* W = (which==0) ? Wq : (which==1) ? Wk : (which==2) ? Wv : Wg;
    int m0 = blockIdx.x * BM;
    int tid = threadIdx.x;
    int tr = tid >> 4;          // 0..15 -> rows tr*8..
    int tc = tid & 15;          // 0..15 -> cols tc*8..
    float acc[8][8];
    #pragma unroll
    for (int x = 0; x < 8; x++)
        #pragma unroll
        for (int y = 0; y < 8; y++) acc[x][y] = 0.f;

    for (int k0 = 0; k0 < DP; k0 += BK) {
        #pragma unroll
        for (int it = 0; it < 4; it++) {
            int idx4 = tid + it*256;            // 1024 float4 in [128][32] tile
            int row = idx4 >> 3;
            int col = (idx4 & 7) * 4;
            float4 v = *(const float4*)(g_pn + (size_t)(m0+row)*DP + k0 + col);
            As[col+0][row] = v.x; As[col+1][row] = v.y;
            As[col+2][row] = v.z; As[col+3][row] = v.w;
        }
        #pragma unroll
        for (int it = 0; it < 4; it++) {
            int idx4 = tid + it*256;            // [32][128] tile
            int row = idx4 >> 5;
            int col = (idx4 & 31) * 4;
            *(float4*)&Bs[row][col] = *(const float4*)(W + (size_t)(k0+row)*DP + col);
        }
        __syncthreads();
        #pragma unroll
        for (int k = 0; k < BK; k++) {
            float4 a0 = *(float4*)&As[k][tr*8];
            float4 a1 = *(float4*)&As[k][tr*8+4];
            float4 b0 = *(float4*)&Bs[k][tc*8];
            float4 b1 = *(float4*)&Bs[k][tc*8+4];
            float a[8] = {a0.x,a0.y,a0.z,a0.w,a1.x,a1.y,a1.z,a1.w};
            float b[8] = {b0.x,b0.y,b0.z,b0.w,b1.x,b1.y,b1.z,b1.w};
            #pragma unroll
            for (int x = 0; x < 8; x++)
                #pragma unroll
                for (int y = 0; y < 8; y++)
                    acc[x][y] += a[x]*b[y];
        }
        __syncthreads();
    }

    const float qscale = 0.17677669529663689f;   // 1/sqrt(32)
    const float kscale = 1.0f / (float)L;
    float* dst = (which==0) ? g_q : (which==1) ? g_k : (which==2) ? g_v : g_gate;
    #pragma unroll
    for (int x = 0; x < 8; x++) {
        int m = m0 + tr*8 + x;
        #pragma unroll
        for (int y = 0; y < 8; y++) {
            int c = tc*8 + y;
            float v = acc[x][y];
            if      (which == 0) v *= qscale;
            else if (which == 1) v *= kscale;
            else if (which == 3) v = 1.0f / (1.0f + expf(-(v + bg[c])));
            dst[(size_t)m*DP + c] = v;
        }
    }
}

// ---------------- kernel 4: QK logits ----------------
// attn[h][i][j] = sum_n sum_d q[n*L+i][h*32+d] * k[n*L+j][h*32+d]
// grid (6,6,4): 64x64 (i,j) tile per head, loop over n.
__global__ __launch_bounds__(256) void k_qk()
{
    __shared__ float Qs[DH][68];   // [d][i]
    __shared__ float Ks[DH][68];   // [d][j]
    int i0 = blockIdx.x * 64;
    int j0 = blockIdx.y * 64;
    int h  = blockIdx.z;
    int tid = threadIdx.x;
    int ti = tid >> 4;      // 0..15 -> i = ti*4..
    int tj = tid & 15;      // 0..15 -> j = tj*4..
    float acc[4][4];
    #pragma unroll
    for (int a = 0; a < 4; a++)
        #pragma unroll
        for (int b = 0; b < 4; b++) acc[a][b] = 0.f;

    for (int n = 0; n < L; n++) {
        #pragma unroll
        for (int it = 0; it < 2; it++) {
            int id = tid + it*256;         // 512 float4 in [64][32]
            int row = id >> 3;
            int col = (id & 7) * 4;
            float4 qv = *(const float4*)(g_q + (size_t)(n*L + i0 + row)*DP + h*DH + col);
            Qs[col+0][row]=qv.x; Qs[col+1][row]=qv.y; Qs[col+2][row]=qv.z; Qs[col+3][row]=qv.w;
            float4 kv = *(const float4*)(g_k + (size_t)(n*L + j0 + row)*DP + h*DH + col);
            Ks[col+0][row]=kv.x; Ks[col+1][row]=kv.y; Ks[col+2][row]=kv.z; Ks[col+3][row]=kv.w;
        }
        __syncthreads();
        #pragma unroll
        for (int d = 0; d < DH; d++) {
            float4 a4 = *(float4*)&Qs[d][ti*4];
            float4 b4 = *(float4*)&Ks[d][tj*4];
            float a[4] = {a4.x,a4.y,a4.z,a4.w};
            float b[4] = {b4.x,b4.y,b4.z,b4.w};
            #pragma unroll
            for (int x = 0; x < 4; x++)
                #pragma unroll
                for (int y = 0; y < 4; y++)
                    acc[x][y] += a[x]*b[y];
        }
        __syncthreads();
    }
    float* dst = g_attn + (size_t)h*LL;
    #pragma unroll
    for (int x = 0; x < 4; x++) {
        int i = i0 + ti*4 + x;
        *(float4*)(dst + (size_t)i*L + j0 + tj*4) =
            make_float4(acc[x][0], acc[x][1], acc[x][2], acc[x][3]);
    }
}

// ---------------- kernel 5: softmax over j (with learned bias added) ----------------
__global__ __launch_bounds__(128) void k_softmax()
{
    __shared__ float redm[4], reds[4];
    int i = blockIdx.x, h = blockIdx.y;
    int tid = threadIdx.x;
    float* qk = g_attn + (size_t)h*LL + (size_t)i*L;
    float v[3];
    float mx = -1e30f;
    #pragma unroll
    for (int r = 0; r < 3; r++) {
        int j = tid + r*128;
        v[r] = qk[j] + g_battn[((size_t)i*L + j)*NH + h];
        mx = fmaxf(mx, v[r]);
    }
    #pragma unroll
    for (int o = 16; o; o >>= 1) mx = fmaxf(mx, __shfl_xor_sync(0xffffffffu, mx, o));
    if ((tid & 31) == 0) redm[tid >> 5] = mx;
    __syncthreads();
    mx = fmaxf(fmaxf(redm[0], redm[1]), fmaxf(redm[2], redm[3]));
    float se = 0.f;
    #pragma unroll
    for (int r = 0; r < 3; r++) { v[r] = expf(v[r] - mx); se += v[r]; }
    #pragma unroll
    for (int o = 16; o; o >>= 1) se += __shfl_xor_sync(0xffffffffu, se, o);
    if ((tid & 31) == 0) reds[tid >> 5] = se;
    __syncthreads();
    se = reds[0] + reds[1] + reds[2] + reds[3];
    float inv = 1.0f / se;
    #pragma unroll
    for (int r = 0; r < 3; r++) qk[tid + r*128] = v[r] * inv;
}

// ---------------- kernel 6: o[n,i,h,d] = sum_j a[h][i][j] * v[n*L+j][h*32+d] ----------------
// grid (384, 4) = (n, h). 256 threads. i in 3 chunks of 128, j in chunks of 32.
__global__ __launch_bounds__(256) void k_o()
{
    __shared__ float As[32][132];   // [j][i]  (i-chunk of 128)
    __shared__ float Vs[32][36];    // [j][d]
    int n = blockIdx.x, h = blockIdx.y;
    int tid = threadIdx.x;
    int ti = tid >> 3;      // 0..31 -> i = ti*4..
    int td = tid & 7;       // 0..7  -> d = td*4..
    const float* A = g_attn + (size_t)h*LL;

    for (int i0 = 0; i0 < L; i0 += 128) {
        float acc[4][4];
        #pragma unroll
        for (int a = 0; a < 4; a++)
            #pragma unroll
            for (int b = 0; b < 4; b++) acc[a][b] = 0.f;

        for (int j0 = 0; j0 < L; j0 += 32) {
            #pragma unroll
            for (int it = 0; it < 4; it++) {
                int idx4 = tid + it*256;         // [128 i][32 j] tile
                int row = idx4 >> 3;             // i
                int col = (idx4 & 7) * 4;        // j
                float4 av = *(const float4*)(A + (size_t)(i0+row)*L + j0 + col);
                As[col+0][row]=av.x; As[col+1][row]=av.y;
                As[col+2][row]=av.z; As[col+3][row]=av.w;
            }
            {
                int row = tid >> 3;              // j (0..31)
                int col = (tid & 7) * 4;         // d
                *(float4*)&Vs[row][col] =
                    *(const float4*)(g_v + (size_t)(n*L + j0 + row)*DP + h*DH + col);
            }
            __syncthreads();
            #pragma unroll
            for (int j = 0; j < 32; j++) {
                float4 a4 = *(float4*)&As[j][ti*4];
                float4 v4 = *(float4*)&Vs[j][td*4];
                float a[4] = {a4.x,a4.y,a4.z,a4.w};
                float b[4] = {v4.x,v4.y,v4.z,v4.w};
                #pragma unroll
                for (int x = 0; x < 4; x++)
                    #pragma unroll
                    for (int y = 0; y < 4; y++)
                        acc[x][y] += a[x]*b[y];
            }
            __syncthreads();
        }
        #pragma unroll
        for (int x = 0; x < 4; x++) {
            int i = i0 + ti*4 + x;
            *(float4*)(g_o + (size_t)(n*L + i)*DP + h*DH + td*4) =
                make_float4(acc[x][0], acc[x][1], acc[x][2], acc[x][3]);
        }
    }
}

// ---------------- kernel 7: out = (gate*o) @ Wout + bout, transposed store ----------------
__global__ __launch_bounds__(256) void k_out(const float* __restrict__ Wout,
                                             const float* __restrict__ bout,
                                             float* __restrict__ out)
{
    __shared__ float As[BK][BM+4];
    __shared__ float Bs[BK][BN];
    int m0 = blockIdx.x * BM;
    int n  = m0 / L;          // constant within tile (128 | 384)
    int ib = m0 % L;
    int tid = threadIdx.x;
    int tr = tid >> 4, tc = tid & 15;
    float acc[8][8];
    #pragma unroll
    for (int x = 0; x < 8; x++)
        #pragma unroll
        for (int y = 0; y < 8; y++) acc[x][y] = 0.f;

    for (int k0 = 0; k0 < DP; k0 += BK) {
        #pragma unroll
        for (int it = 0; it < 4; it++) {
            int idx4 = tid + it*256;
            int row = idx4 >> 3;
            int col = (idx4 & 7) * 4;
            size_t base = (size_t)(m0+row)*DP + k0 + col;
            float4 ov = *(const float4*)(g_o + base);
            float4 gv = *(const float4*)(g_gate + base);
            As[col+0][row] = ov.x*gv.x; As[col+1][row] = ov.y*gv.y;
            As[col+2][row] = ov.z*gv.z; As[col+3][row] = ov.w*gv.w;
        }
        #pragma unroll
        for (int it = 0; it < 4; it++) {
            int idx4 = tid + it*256;
            int row = idx4 >> 5;
            int col = (idx4 & 31) * 4;
            *(float4*)&Bs[row][col] = *(const float4*)(Wout + (size_t)(k0+row)*DP + col);
        }
        __syncthreads();
        #pragma unroll
        for (int k = 0; k < BK; k++) {
            float4 a0 = *(float4*)&As[k][tr*8];
            float4 a1 = *(float4*)&As[k][tr*8+4];
            float4 b0 = *(float4*)&Bs[k][tc*8];
            float4 b1 = *(float4*)&Bs[k][tc*8+4];
            float a[8] = {a0.x,a0.y,a0.z,a0.w,a1.x,a1.y,a1.z,a1.w};
            float b[8] = {b0.x,b0.y,b0.z,b0.w,b1.x,b1.y,b1.z,b1.w};
            #pragma unroll
            for (int x = 0; x < 8; x++)
                #pragma unroll
                for (int y = 0; y < 8; y++)
                    acc[x][y] += a[x]*b[y];
        }
        __syncthreads();
    }
    // final layout: out[b, i, n, c]  (undo is_row transpose)
    #pragma unroll
    for (int x = 0; x < 8; x++) {
        int i = ib + tr*8 + x;
        size_t row = (size_t)i*L + n;
        #pragma unroll
        for (int y = 0; y < 8; y++) {
            int c = tc*8 + y;
            out[row*DP + c] = acc[x][y] + bout[c];
        }
    }
}

// ---------------- launch ----------------
extern "C" void kernel_launch(void* const* d_in, const int* in_sizes, int n_in,
                              void* d_out, int out_size)
{
    const float* pair    = (const float*)d_in[0];
    const float* bias    = (const float*)d_in[1];
    const float* gamma_p = (const float*)d_in[2];
    const float* beta_p  = (const float*)d_in[3];
    const float* gamma_b = (const float*)d_in[4];
    const float* beta_b  = (const float*)d_in[5];
    const float* Wq      = (const float*)d_in[6];
    const float* Wk      = (const float*)d_in[7];
    const float* Wv      = (const float*)d_in[8];
    const float* Wb      = (const float*)d_in[9];
    const float* Wg      = (const float*)d_in[10];
    const float* bg      = (const float*)d_in[11];
    const float* Wout    = (const float*)d_in[12];
    const float* bout    = (const float*)d_in[13];
    float* out = (float*)d_out;

    k_ln_pair<<<LL/8, 256>>>(pair, gamma_p, beta_p);
    k_bias  <<<LL/8, 256>>>(bias, gamma_b, beta_b, Wb);
    k_proj  <<<dim3(LL/BM, 4), 256>>>(Wq, Wk, Wv, Wg, bg);
    k_qk    <<<dim3(L/64, L/64, NH), 256>>>();
    k_softmax<<<dim3(L, NH), 128>>>();
    k_o     <<<dim3(L, NH), 256>>>();
    k_out   <<<LL/BM, 256>>>(Wout, bout, out);
}

// round 2
// speedup vs baseline: 2.8484x; 2.8484x over previous
#include <cuda_runtime.h>
#include <math.h>

#define L    384
#define DP   128
#define NH   4
#define DH   32
#define LL   (L*L)            // 147456
#define SPLIT 16
#define NSPL  (L/SPLIT)       // 24 n per qk split

// ---------------- scratch ----------------
__device__ float g_pn  [LL*DP];         // LN(pair_t), row p = n*L + i
__device__ float g_q   [LL*DP];         // pn @ Wq * 1/sqrt(d)
__device__ float g_k   [LL*DP];         // pn @ Wk / L
__device__ float g_vT  [NH*LL*DH];      // v transposed: [h][j][n][d] -> (h*L+j)*L*32 + n*32 + d
__device__ float g_gate[LL*DP];         // sigmoid(pn @ Wg + bg)
__device__ float g_o   [LL*DP];         // attention output (pre-gate), row n*L+i
__device__ float g_attn[NH*LL];         // softmax probs [h][i][j]
__device__ float g_battn[LL*NH];        // [(i*L+j)*4 + h]
__device__ float g_qkp [SPLIT*NH*LL];   // qk partials [s][h][i][j]

// ---------------- helpers ----------------
__device__ __forceinline__ float tf32r(float x) {
    float y; asm("cvt.rna.tf32.f32 %0, %1;" : "=f"(y) : "f"(x)); return y;
}
__device__ __forceinline__ void mma8(float c[4], const float a[4], const float b[2]) {
    asm volatile(
        "mma.sync.aligned.m16n8k8.row.col.f32.tf32.tf32.f32 "
        "{%0,%1,%2,%3},{%4,%5,%6,%7},{%8,%9},{%0,%1,%2,%3};\n"
        : "+f"(c[0]), "+f"(c[1]), "+f"(c[2]), "+f"(c[3])
        : "r"(__float_as_uint(a[0])), "r"(__float_as_uint(a[1])),
          "r"(__float_as_uint(a[2])), "r"(__float_as_uint(a[3])),
          "r"(__float_as_uint(b[0])), "r"(__float_as_uint(b[1])));
}

// ---------------- kernel 1: layernorm of transposed pair ----------------
__global__ __launch_bounds__(256) void k_ln_pair(const float* __restrict__ pair,
                                                 const float* __restrict__ gamma,
                                                 const float* __restrict__ beta)
{
    int warp = (blockIdx.x * blockDim.x + threadIdx.x) >> 5;
    int lane = threadIdx.x & 31;
    if (warp >= LL) return;
    int n = warp / L, i = warp % L;
    float4 x = ((const float4*)(pair + (size_t)(i*L + n) * DP))[lane];
    float s  = x.x + x.y + x.z + x.w;
    float ss = x.x*x.x + x.y*x.y + x.z*x.z + x.w*x.w;
    #pragma unroll
    for (int o = 16; o; o >>= 1) {
        s  += __shfl_xor_sync(0xffffffffu, s,  o);
        ss += __shfl_xor_sync(0xffffffffu, ss, o);
    }
    float mean = s * (1.0f/DP);
    float var  = ss * (1.0f/DP) - mean*mean;
    float inv  = rsqrtf(var + 1e-5f);
    float4 g = ((const float4*)gamma)[lane];
    float4 b = ((const float4*)beta )[lane];
    float4 y;
    y.x = (x.x - mean)*inv*g.x + b.x;
    y.y = (x.y - mean)*inv*g.y + b.y;
    y.z = (x.z - mean)*inv*g.z + b.z;
    y.w = (x.w - mean)*inv*g.w + b.w;
    ((float4*)(g_pn + (size_t)warp * DP))[lane] = y;
}

// ---------------- kernel 2: bias path ----------------
__global__ __launch_bounds__(256) void k_bias(const float* __restrict__ bias,
                                              const float* __restrict__ gamma,
                                              const float* __restrict__ beta,
                                              const float* __restrict__ Wb)
{
    int warp = (blockIdx.x * blockDim.x + threadIdx.x) >> 5;
    int lane = threadIdx.x & 31;
    if (warp >= LL) return;
    int i = warp / L, j = warp % L;
    float4 x = ((const float4*)(bias + (size_t)(j*L + i) * DP))[lane];
    float s  = x.x + x.y + x.z + x.w;
    float ss = x.x*x.x + x.y*x.y + x.z*x.z + x.w*x.w;
    #pragma unroll
    for (int o = 16; o; o >>= 1) {
        s  += __shfl_xor_sync(0xffffffffu, s,  o);
        ss += __shfl_xor_sync(0xffffffffu, ss, o);
    }
    float mean = s * (1.0f/DP);
    float var  = ss * (1.0f/DP) - mean*mean;
    float inv  = rsqrtf(var + 1e-5f);
    float4 g = ((const float4*)gamma)[lane];
    float4 b = ((const float4*)beta )[lane];
    float y[4];
    y[0] = (x.x - mean)*inv*g.x + b.x;
    y[1] = (x.y - mean)*inv*g.y + b.y;
    y[2] = (x.z - mean)*inv*g.z + b.z;
    y[3] = (x.w - mean)*inv*g.w + b.w;
    float acc[NH] = {0.f, 0.f, 0.f, 0.f};
    #pragma unroll
    for (int t = 0; t < 4; t++) {
        int c = lane*4 + t;
        #pragma unroll
        for (int h = 0; h < NH; h++)
            acc[h] += y[t] * Wb[c*NH + h];
    }
    #pragma unroll
    for (int h = 0; h < NH; h++)
        #pragma unroll
        for (int o = 16; o; o >>= 1)
            acc[h] += __shfl_xor_sync(0xffffffffu, acc[h], o);
    if (lane == 0)
        *(float4*)(g_battn + (size_t)warp * NH) = make_float4(acc[0], acc[1], acc[2], acc[3]);
}

// ---------------- kernel 3: projections, tf32 MMA ----------------
// C[147456,128] = pn @ W, one weight per blockIdx.y.  8 warps: 4(m) x 2(n).
__global__ __launch_bounds__(256) void k_proj(const float* __restrict__ Wq,
                                              const float* __restrict__ Wk,
                                              const float* __restrict__ Wv,
                                              const float* __restrict__ Wg,
                                              const float* __restrict__ bg)
{
    __shared__ float As[128][36];   // [m][k]
    __shared__ float Bs[32][132];   // [k][n]
    int which = blockIdx.y;
    const float* W = (which==0) ? Wq : (which==1) ? Wk : (which==2) ? Wv : Wg;
    int m0 = blockIdx.x * 128;
    int tid = threadIdx.x;
    int w = tid >> 5, lane = tid & 31;
    int wm = w >> 1, wn = w & 1;
    int lrow = lane >> 2, lq = lane & 3;
    float acc[2][8][4];
    #pragma unroll
    for (int mt = 0; mt < 2; mt++)
        #pragma unroll
        for (int nt = 0; nt < 8; nt++)
            #pragma unroll
            for (int r = 0; r < 4; r++) acc[mt][nt][r] = 0.f;

    for (int k0 = 0; k0 < DP; k0 += 32) {
        #pragma unroll
        for (int it = 0; it < 4; it++) {
            int idx4 = tid + it*256;
            int row = idx4 >> 3, col = (idx4 & 7) * 4;
            float4 v = *(const float4*)(g_pn + (size_t)(m0+row)*DP + k0 + col);
            *(float4*)&As[row][col] =
                make_float4(tf32r(v.x), tf32r(v.y), tf32r(v.z), tf32r(v.w));
        }
        #pragma unroll
        for (int it = 0; it < 4; it++) {
            int idx4 = tid + it*256;
            int row = idx4 >> 5, col = (idx4 & 31) * 4;
            float4 v = *(const float4*)(W + (size_t)(k0+row)*DP + col);
            *(float4*)&Bs[row][col] =
                make_float4(tf32r(v.x), tf32r(v.y), tf32r(v.z), tf32r(v.w));
        }
        __syncthreads();
        #pragma unroll
        for (int ks = 0; ks < 4; ks++) {
            int kk = ks*8;
            float a[2][4], b[8][2];
            #pragma unroll
            for (int mt = 0; mt < 2; mt++) {
                int mr = wm*32 + mt*16 + lrow;
                a[mt][0] = As[mr  ][kk+lq];
                a[mt][1] = As[mr+8][kk+lq];
                a[mt][2] = As[mr  ][kk+lq+4];
                a[mt][3] = As[mr+8][kk+lq+4];
            }
            #pragma unroll
            for (int nt = 0; nt < 8; nt++) {
                int nb = wn*64 + nt*8 + lrow;
                b[nt][0] = Bs[kk+lq  ][nb];
                b[nt][1] = Bs[kk+lq+4][nb];
            }
            #pragma unroll
            for (int mt = 0; mt < 2; mt++)
                #pragma unroll
                for (int nt = 0; nt < 8; nt++)
                    mma8(acc[mt][nt], a[mt], b[nt]);
        }
        __syncthreads();
    }

    const float qscale = 0.17677669529663689f;
    const float kscale = 1.0f / (float)L;
    #pragma unroll
    for (int mt = 0; mt < 2; mt++) {
        #pragma unroll
        for (int half = 0; half < 2; half++) {
            int m = m0 + wm*32 + mt*16 + lrow + half*8;
            #pragma unroll
            for (int nt = 0; nt < 8; nt++) {
                int c = wn*64 + nt*8 + 2*lq;
                float v0 = acc[mt][nt][half*2+0];
                float v1 = acc[mt][nt][half*2+1];
                if (which == 0) { v0 *= qscale; v1 *= qscale;
                    *(float2*)(g_q + (size_t)m*DP + c) = make_float2(v0, v1);
                } else if (which == 1) { v0 *= kscale; v1 *= kscale;
                    *(float2*)(g_k + (size_t)m*DP + c) = make_float2(v0, v1);
                } else if (which == 2) {
                    // scatter transposed: m = n*L + j, col c = h*32 + d
                    int n = m / L, j = m % L;
                    int h = c >> 5, d = c & 31;
                    *(float2*)(g_vT + ((size_t)(h*L + j)*L + n)*DH + d) = make_float2(v0, v1);
                } else {
                    v0 = 1.0f/(1.0f + expf(-(v0 + bg[c  ])));
                    v1 = 1.0f/(1.0f + expf(-(v1 + bg[c+1])));
                    *(float2*)(g_gate + (size_t)m*DP + c) = make_float2(v0, v1);
                }
            }
        }
    }
}

// ---------------- kernel 4: QK logits, tf32 MMA, split-K ----------------
// partial[s][h][i][j] = sum_{n in split s} sum_d q[n,i,hd] k[n,j,hd]
__global__ __launch_bounds__(256) void k_qk()
{
    __shared__ float As[128][36];   // q: [i][d]
    __shared__ float Bs[128][36];   // k: [j][d]
    int i0 = blockIdx.x * 128;
    int j0 = blockIdx.y * 128;
    int h  = blockIdx.z & 3;
    int s  = blockIdx.z >> 2;
    int tid = threadIdx.x;
    int w = tid >> 5, lane = tid & 31;
    int wm = w >> 1, wn = w & 1;
    int lrow = lane >> 2, lq = lane & 3;
    float acc[2][8][4];
    #pragma unroll
    for (int mt = 0; mt < 2; mt++)
        #pragma unroll
        for (int nt = 0; nt < 8; nt++)
            #pragma unroll
            for (int r = 0; r < 4; r++) acc[mt][nt][r] = 0.f;

    for (int nn = 0; nn < NSPL; nn++) {
        int n = s*NSPL + nn;
        #pragma unroll
        for (int it = 0; it < 4; it++) {
            int idx4 = tid + it*256;
            int row = idx4 >> 3, col = (idx4 & 7) * 4;
            float4 qv = *(const float4*)(g_q + (size_t)(n*L + i0 + row)*DP + h*DH + col);
            *(float4*)&As[row][col] =
                make_float4(tf32r(qv.x), tf32r(qv.y), tf32r(qv.z), tf32r(qv.w));
            float4 kv = *(const float4*)(g_k + (size_t)(n*L + j0 + row)*DP + h*DH + col);
            *(float4*)&Bs[row][col] =
                make_float4(tf32r(kv.x), tf32r(kv.y), tf32r(kv.z), tf32r(kv.w));
        }
        __syncthreads();
        #pragma unroll
        for (int ks = 0; ks < 4; ks++) {
            int kk = ks*8;
            float a[2][4], b[8][2];
            #pragma unroll
            for (int mt = 0; mt < 2; mt++) {
                int mr = wm*32 + mt*16 + lrow;
                a[mt][0] = As[mr  ][kk+lq];
                a[mt][1] = As[mr+8][kk+lq];
                a[mt][2] = As[mr  ][kk+lq+4];
                a[mt][3] = As[mr+8][kk+lq+4];
            }
            #pragma unroll
            for (int nt = 0; nt < 8; nt++) {
                int nb = wn*64 + nt*8 + lrow;
                b[nt][0] = Bs[nb][kk+lq];
                b[nt][1] = Bs[nb][kk+lq+4];
            }
            #pragma unroll
            for (int mt = 0; mt < 2; mt++)
                #pragma unroll
                for (int nt = 0; nt < 8; nt++)
                    mma8(acc[mt][nt], a[mt], b[nt]);
        }
        __syncthreads();
    }
    float* dst = g_qkp + (size_t)(s*NH + h)*LL;
    #pragma unroll
    for (int mt = 0; mt < 2; mt++)
        #pragma unroll
        for (int half = 0; half < 2; half++) {
            int i = i0 + wm*32 + mt*16 + lrow + half*8;
            #pragma unroll
            for (int nt = 0; nt < 8; nt++) {
                int j = j0 + wn*64 + nt*8 + 2*lq;
                *(float2*)(dst + (size_t)i*L + j) =
                    make_float2(acc[mt][nt][half*2], acc[mt][nt][half*2+1]);
            }
        }
}

// ---------------- kernel 5: softmax (fused split-K reduce + bias) ----------------
__global__ __launch_bounds__(128) void k_softmax()
{
    __shared__ float redm[4], reds[4];
    int i = blockIdx.x, h = blockIdx.y;
    int tid = threadIdx.x;
    float v[3];
    float mx = -1e30f;
    #pragma unroll
    for (int r = 0; r < 3; r++) {
        int j = tid + r*128;
        float a = g_battn[((size_t)i*L + j)*NH + h];
        #pragma unroll
        for (int s = 0; s < SPLIT; s++)
            a += g_qkp[(size_t)(s*NH + h)*LL + (size_t)i*L + j];
        v[r] = a;
        mx = fmaxf(mx, a);
    }
    #pragma unroll
    for (int o = 16; o; o >>= 1) mx = fmaxf(mx, __shfl_xor_sync(0xffffffffu, mx, o));
    if ((tid & 31) == 0) redm[tid >> 5] = mx;
    __syncthreads();
    mx = fmaxf(fmaxf(redm[0], redm[1]), fmaxf(redm[2], redm[3]));
    float se = 0.f;
    #pragma unroll
    for (int r = 0; r < 3; r++) { v[r] = expf(v[r] - mx); se += v[r]; }
    #pragma unroll
    for (int o = 16; o; o >>= 1) se += __shfl_xor_sync(0xffffffffu, se, o);
    if ((tid & 31) == 0) reds[tid >> 5] = se;
    __syncthreads();
    se = reds[0] + reds[1] + reds[2] + reds[3];
    float inv = 1.0f / se;
    float* dst = g_attn + (size_t)h*LL + (size_t)i*L;
    #pragma unroll
    for (int r = 0; r < 3; r++) dst[tid + r*128] = v[r] * inv;
}

// ---------------- kernel 6: AV as per-head GEMM, tf32 MMA ----------------
// O[i, nd] = sum_j attn[h][i][j] * vT[h][j][nd],  M=384, N=12288, K=384
__global__ __launch_bounds__(256) void k_o()
{
    __shared__ float As[128][36];   // attn: [i][j]
    __shared__ float Bs[32][132];   // vT:   [j][nd]
    int i0  = blockIdx.x * 128;
    int nd0 = blockIdx.y * 128;
    int h   = blockIdx.z;
    int tid = threadIdx.x;
    int w = tid >> 5, lane = tid & 31;
    int wm = w >> 1, wn = w & 1;
    int lrow = lane >> 2, lq = lane & 3;
    const float* A = g_attn + (size_t)h*LL;
    const float* B = g_vT + (size_t)h*L*L*DH;
    float acc[2][8][4];
    #pragma unroll
    for (int mt = 0; mt < 2; mt++)
        #pragma unroll
        for (int nt = 0; nt < 8; nt++)
            #pragma unroll
            for (int r = 0; r < 4; r++) acc[mt][nt][r] = 0.f;

    for (int k0 = 0; k0 < L; k0 += 32) {
        #pragma unroll
        for (int it = 0; it < 4; it++) {
            int idx4 = tid + it*256;
            int row = idx4 >> 3, col = (idx4 & 7) * 4;
            float4 v = *(const float4*)(A + (size_t)(i0+row)*L + k0 + col);
            *(float4*)&As[row][col] =
                make_float4(tf32r(v.x), tf32r(v.y), tf32r(v.z), tf32r(v.w));
        }
        #pragma unroll
        for (int it = 0; it < 4; it++) {
            int idx4 = tid + it*256;
            int row = idx4 >> 5, col = (idx4 & 31) * 4;
            float4 v = *(const float4*)(B + (size_t)(k0+row)*(L*DH) + nd0 + col);
            *(float4*)&Bs[row][col] =
                make_float4(tf32r(v.x), tf32r(v.y), tf32r(v.z), tf32r(v.w));
        }
        __syncthreads();
        #pragma unroll
        for (int ks = 0; ks < 4; ks++) {
            int kk = ks*8;
            float a[2][4], b[8][2];
            #pragma unroll
            for (int mt = 0; mt < 2; mt++) {
                int mr = wm*32 + mt*16 + lrow;
                a[mt][0] = As[mr  ][kk+lq];
                a[mt][1] = As[mr+8][kk+lq];
                a[mt][2] = As[mr  ][kk+lq+4];
                a[mt][3] = As[mr+8][kk+lq+4];
            }
            #pragma unroll
            for (int nt = 0; nt < 8; nt++) {
                int nb = wn*64 + nt*8 + lrow;
                b[nt][0] = Bs[kk+lq  ][nb];
                b[nt][1] = Bs[kk+lq+4][nb];
            }
            #pragma unroll
            for (int mt = 0; mt < 2; mt++)
                #pragma unroll
                for (int nt = 0; nt < 8; nt++)
                    mma8(acc[mt][nt], a[mt], b[nt]);
        }
        __syncthreads();
    }
    #pragma unroll
    for (int mt = 0; mt < 2; mt++)
        #pragma unroll
        for (int half = 0; half < 2; half++) {
            int i = i0 + wm*32 + mt*16 + lrow + half*8;
            #pragma unroll
            for (int nt = 0; nt < 8; nt++) {
                int nd = nd0 + wn*64 + nt*8 + 2*lq;
                int n = nd >> 5, d = nd & 31;
                *(float2*)(g_o + (size_t)(n*L + i)*DP + h*DH + d) =
                    make_float2(acc[mt][nt][half*2], acc[mt][nt][half*2+1]);
            }
        }
}

// ---------------- kernel 7: out = (gate*o) @ Wout + bout, tf32 MMA ----------------
__global__ __launch_bounds__(256) void k_out(const float* __restrict__ Wout,
                                             const float* __restrict__ bout,
                                             float* __restrict__ out)
{
    __shared__ float As[128][36];
    __shared__ float Bs[32][132];
    int m0 = blockIdx.x * 128;
    int n  = m0 / L;
    int ib = m0 % L;
    int tid = threadIdx.x;
    int w = tid >> 5, lane = tid & 31;
    int wm = w >> 1, wn = w & 1;
    int lrow = lane >> 2, lq = lane & 3;
    float acc[2][8][4];
    #pragma unroll
    for (int mt = 0; mt < 2; mt++)
        #pragma unroll
        for (int nt = 0; nt < 8; nt++)
            #pragma unroll
            for (int r = 0; r < 4; r++) acc[mt][nt][r] = 0.f;

    for (int k0 = 0; k0 < DP; k0 += 32) {
        #pragma unroll
        for (int it = 0; it < 4; it++) {
            int idx4 = tid + it*256;
            int row = idx4 >> 3, col = (idx4 & 7) * 4;
            size_t base = (size_t)(m0+row)*DP + k0 + col;
            float4 ov = *(const float4*)(g_o + base);
            float4 gv = *(const float4*)(g_gate + base);
            *(float4*)&As[row][col] =
                make_float4(tf32r(ov.x*gv.x), tf32r(ov.y*gv.y),
                            tf32r(ov.z*gv.z), tf32r(ov.w*gv.w));
        }
        #pragma unroll
        for (int it = 0; it < 4; it++) {
            int idx4 = tid + it*256;
            int row = idx4 >> 5, col = (idx4 & 31) * 4;
            float4 v = *(const float4*)(Wout + (size_t)(k0+row)*DP + col);
            *(float4*)&Bs[row][col] =
                make_float4(tf32r(v.x), tf32r(v.y), tf32r(v.z), tf32r(v.w));
        }
        __syncthreads();
        #pragma unroll
        for (int ks = 0; ks < 4; ks++) {
            int kk = ks*8;
            float a[2][4], b[8][2];
            #pragma unroll
            for (int mt = 0; mt < 2; mt++) {
                int mr = wm*32 + mt*16 + lrow;
                a[mt][0] = As[mr  ][kk+lq];
                a[mt][1] = As[mr+8][kk+lq];
                a[mt][2] = As[mr  ][kk+lq+4];
                a[mt][3] = As[mr+8][kk+lq+4];
            }
            #pragma unroll
            for (int nt = 0; nt < 8; nt++) {
                int nb = wn*64 + nt*8 + lrow;
                b[nt][0] = Bs[kk+lq  ][nb];
                b[nt][1] = Bs[kk+lq+4][nb];
            }
            #pragma unroll
            for (int mt = 0; mt < 2; mt++)
                #pragma unroll
                for (int nt = 0; nt < 8; nt++)
                    mma8(acc[mt][nt], a[mt], b[nt]);
        }
        __syncthreads();
    }
    // store out[b, i, n, c] (undo is_row transpose)
    #pragma unroll
    for (int mt = 0; mt < 2; mt++)
        #pragma unroll
        for (int half = 0; half < 2; half++) {
            int i = ib + wm*32 + mt*16 + lrow + half*8;
            size_t row = (size_t)i*L + n;
            #pragma unroll
            for (int nt = 0; nt < 8; nt++) {
                int c = wn*64 + nt*8 + 2*lq;
                *(float2*)(out + row*DP + c) =
                    make_float2(acc[mt][nt][half*2]   + bout[c],
                                acc[mt][nt][half*2+1] + bout[c+1]);
            }
        }
}

// ---------------- launch ----------------
extern "C" void kernel_launch(void* const* d_in, const int* in_sizes, int n_in,
                              void* d_out, int out_size)
{
    const float* pair    = (const float*)d_in[0];
    const float* bias    = (const float*)d_in[1];
    const float* gamma_p = (const float*)d_in[2];
    const float* beta_p  = (const float*)d_in[3];
    const float* gamma_b = (const float*)d_in[4];
    const float* beta_b  = (const float*)d_in[5];
    const float* Wq      = (const float*)d_in[6];
    const float* Wk      = (const float*)d_in[7];
    const float* Wv      = (const float*)d_in[8];
    const float* Wb      = (const float*)d_in[9];
    const float* Wg      = (const float*)d_in[10];
    const float* bg      = (const float*)d_in[11];
    const float* Wout    = (const float*)d_in[12];
    const float* bout    = (const float*)d_in[13];
    float* out = (float*)d_out;

    k_ln_pair <<<LL/8, 256>>>(pair, gamma_p, beta_p);
    k_bias    <<<LL/8, 256>>>(bias, gamma_b, beta_b, Wb);
    k_proj    <<<dim3(LL/128, 4), 256>>>(Wq, Wk, Wv, Wg, bg);
    k_qk      <<<dim3(3, 3, NH*SPLIT), 256>>>();
    k_softmax <<<dim3(L, NH), 128>>>();
    k_o       <<<dim3(3, (L*DH)/128, NH), 256>>>();
    k_out     <<<LL/128, 256>>>(Wout, bout, out);
}

// round 3
// speedup vs baseline: 3.3663x; 1.1818x over previous
#include <cuda_runtime.h>
#include <cuda_bf16.h>
#include <math.h>

#define L    384
#define DP   128
#define NH   4
#define DH   32
#define LL   (L*L)            // 147456
#define SPLIT 16
#define NSPL  (L/SPLIT)       // 24

// ---------------- scratch ----------------
__device__ float g_pn  [LL*DP];              // LN(pair_t), tf32-rounded, row p = n*L+i
__device__ __nv_bfloat16 g_qb[NH*LL*DH];     // q bf16: ((h*L+n)*L+i)*32+d
__device__ __nv_bfloat16 g_kb[NH*LL*DH];     // k bf16: ((h*L+n)*L+j)*32+d
__device__ float g_vT  [NH*LL*DH];           // v tf32-rounded: ((h*L+j)*L+n)*32+d
__device__ float g_gate[LL*DP];
__device__ float g_o   [LL*DP];              // row n*L+i
__device__ float g_attn[NH*LL];              // softmax probs, tf32-rounded
__device__ float g_battn[LL*NH];
__device__ float g_qkp [SPLIT*NH*LL];        // qk partials [s][h][i][j]

// ---------------- helpers ----------------
__device__ __forceinline__ float tf32r(float x) {
    float y; asm("cvt.rna.tf32.f32 %0, %1;" : "=f"(y) : "f"(x)); return y;
}
__device__ __forceinline__ void cpa16(void* dst, const void* src) {
    unsigned d = (unsigned)__cvta_generic_to_shared(dst);
    asm volatile("cp.async.cg.shared.global [%0], [%1], 16;\n" :: "r"(d), "l"(src));
}
#define CPA_COMMIT asm volatile("cp.async.commit_group;\n" ::: "memory")
#define CPA_WAIT0  asm volatile("cp.async.wait_group 0;\n" ::: "memory")

__device__ __forceinline__ void mma8(float c[4], const float a[4], const float b[2]) {
    asm volatile(
        "mma.sync.aligned.m16n8k8.row.col.f32.tf32.tf32.f32 "
        "{%0,%1,%2,%3},{%4,%5,%6,%7},{%8,%9},{%0,%1,%2,%3};\n"
        : "+f"(c[0]), "+f"(c[1]), "+f"(c[2]), "+f"(c[3])
        : "r"(__float_as_uint(a[0])), "r"(__float_as_uint(a[1])),
          "r"(__float_as_uint(a[2])), "r"(__float_as_uint(a[3])),
          "r"(__float_as_uint(b[0])), "r"(__float_as_uint(b[1])));
}
__device__ __forceinline__ void mma16(float c[4], const unsigned a[4], const unsigned b[2]) {
    asm volatile(
        "mma.sync.aligned.m16n8k16.row.col.f32.bf16.bf16.f32 "
        "{%0,%1,%2,%3},{%4,%5,%6,%7},{%8,%9},{%0,%1,%2,%3};\n"
        : "+f"(c[0]), "+f"(c[1]), "+f"(c[2]), "+f"(c[3])
        : "r"(a[0]), "r"(a[1]), "r"(a[2]), "r"(a[3]), "r"(b[0]), "r"(b[1]));
}

// ---------------- kernel 1: layernorm of transposed pair (tf32-rounded store) ----------------
__global__ __launch_bounds__(256) void k_ln_pair(const float* __restrict__ pair,
                                                 const float* __restrict__ gamma,
                                                 const float* __restrict__ beta)
{
    int warp = (blockIdx.x * blockDim.x + threadIdx.x) >> 5;
    int lane = threadIdx.x & 31;
    if (warp >= LL) return;
    int n = warp / L, i = warp % L;
    float4 x = ((const float4*)(pair + (size_t)(i*L + n) * DP))[lane];
    float s  = x.x + x.y + x.z + x.w;
    float ss = x.x*x.x + x.y*x.y + x.z*x.z + x.w*x.w;
    #pragma unroll
    for (int o = 16; o; o >>= 1) {
        s  += __shfl_xor_sync(0xffffffffu, s,  o);
        ss += __shfl_xor_sync(0xffffffffu, ss, o);
    }
    float mean = s * (1.0f/DP);
    float var  = ss * (1.0f/DP) - mean*mean;
    float inv  = rsqrtf(var + 1e-5f);
    float4 g = ((const float4*)gamma)[lane];
    float4 b = ((const float4*)beta )[lane];
    float4 y;
    y.x = tf32r((x.x - mean)*inv*g.x + b.x);
    y.y = tf32r((x.y - mean)*inv*g.y + b.y);
    y.z = tf32r((x.z - mean)*inv*g.z + b.z);
    y.w = tf32r((x.w - mean)*inv*g.w + b.w);
    ((float4*)(g_pn + (size_t)warp * DP))[lane] = y;
}

// ---------------- kernel 2: bias path ----------------
__global__ __launch_bounds__(256) void k_bias(const float* __restrict__ bias,
                                              const float* __restrict__ gamma,
                                              const float* __restrict__ beta,
                                              const float* __restrict__ Wb)
{
    int warp = (blockIdx.x * blockDim.x + threadIdx.x) >> 5;
    int lane = threadIdx.x & 31;
    if (warp >= LL) return;
    int i = warp / L, j = warp % L;
    float4 x = ((const float4*)(bias + (size_t)(j*L + i) * DP))[lane];
    float s  = x.x + x.y + x.z + x.w;
    float ss = x.x*x.x + x.y*x.y + x.z*x.z + x.w*x.w;
    #pragma unroll
    for (int o = 16; o; o >>= 1) {
        s  += __shfl_xor_sync(0xffffffffu, s,  o);
        ss += __shfl_xor_sync(0xffffffffu, ss, o);
    }
    float mean = s * (1.0f/DP);
    float var  = ss * (1.0f/DP) - mean*mean;
    float inv  = rsqrtf(var + 1e-5f);
    float4 g = ((const float4*)gamma)[lane];
    float4 b = ((const float4*)beta )[lane];
    float y[4];
    y[0] = (x.x - mean)*inv*g.x + b.x;
    y[1] = (x.y - mean)*inv*g.y + b.y;
    y[2] = (x.z - mean)*inv*g.z + b.z;
    y[3] = (x.w - mean)*inv*g.w + b.w;
    float acc[NH] = {0.f, 0.f, 0.f, 0.f};
    #pragma unroll
    for (int t = 0; t < 4; t++) {
        int c = lane*4 + t;
        #pragma unroll
        for (int h = 0; h < NH; h++)
            acc[h] += y[t] * Wb[c*NH + h];
    }
    #pragma unroll
    for (int h = 0; h < NH; h++)
        #pragma unroll
        for (int o = 16; o; o >>= 1)
            acc[h] += __shfl_xor_sync(0xffffffffu, acc[h], o);
    if (lane == 0)
        *(float4*)(g_battn + (size_t)warp * NH) = make_float4(acc[0], acc[1], acc[2], acc[3]);
}

// ---------------- kernel 3: projections, tf32 MMA, cp.async pipelined A ----------------
#define PADA 36
#define PADB 136
__global__ __launch_bounds__(256) void k_proj(const float* __restrict__ Wq,
                                              const float* __restrict__ Wk,
                                              const float* __restrict__ Wv,
                                              const float* __restrict__ Wg,
                                              const float* __restrict__ bg)
{
    extern __shared__ float sm[];
    float (*As)[128][PADA] = (float(*)[128][PADA])sm;              // 2 stages
    float (*Bs)[PADB]      = (float(*)[PADB])(sm + 2*128*PADA);    // [128][PADB]
    int which = blockIdx.y;
    const float* W = (which==0) ? Wq : (which==1) ? Wk : (which==2) ? Wv : Wg;
    int m0 = blockIdx.x * 128;
    int tid = threadIdx.x;
    int w = tid >> 5, lane = tid & 31;
    int wm = w >> 1, wn = w & 1;
    int lrow = lane >> 2, lq = lane & 3;

    // load whole W into smem (tf32-rounded)
    #pragma unroll
    for (int it = 0; it < 16; it++) {
        int idx4 = tid + it*256;
        int row = idx4 >> 5, col = (idx4 & 31) * 4;
        float4 v = *(const float4*)(W + (size_t)row*DP + col);
        Bs[row][col+0] = tf32r(v.x); Bs[row][col+1] = tf32r(v.y);
        Bs[row][col+2] = tf32r(v.z); Bs[row][col+3] = tf32r(v.w);
    }

    auto loadA = [&](int st, int k0) {
        #pragma unroll
        for (int it = 0; it < 4; it++) {
            int cid = tid + it*256;
            int row = cid >> 3, part = cid & 7;
            cpa16(&As[st][row][part*4], g_pn + (size_t)(m0+row)*DP + k0 + part*4);
        }
    };

    float acc[2][8][4];
    #pragma unroll
    for (int mt = 0; mt < 2; mt++)
        #pragma unroll
        for (int nt = 0; nt < 8; nt++)
            #pragma unroll
            for (int r = 0; r < 4; r++) acc[mt][nt][r] = 0.f;

    loadA(0, 0); CPA_COMMIT;
    for (int kt = 0; kt < 4; kt++) {
        CPA_WAIT0; __syncthreads();
        if (kt < 3) { loadA((kt+1)&1, (kt+1)*32); CPA_COMMIT; }
        int st = kt & 1;
        #pragma unroll
        for (int ks = 0; ks < 4; ks++) {
            int kk = ks*8;
            float a[2][4], b[8][2];
            #pragma unroll
            for (int mt = 0; mt < 2; mt++) {
                int mr = wm*32 + mt*16 + lrow;
                a[mt][0] = As[st][mr  ][kk+lq];
                a[mt][1] = As[st][mr+8][kk+lq];
                a[mt][2] = As[st][mr  ][kk+lq+4];
                a[mt][3] = As[st][mr+8][kk+lq+4];
            }
            #pragma unroll
            for (int nt = 0; nt < 8; nt++) {
                int nb = wn*64 + nt*8 + lrow;
                b[nt][0] = Bs[kt*32+kk+lq  ][nb];
                b[nt][1] = Bs[kt*32+kk+lq+4][nb];
            }
            #pragma unroll
            for (int mt = 0; mt < 2; mt++)
                #pragma unroll
                for (int nt = 0; nt < 8; nt++)
                    mma8(acc[mt][nt], a[mt], b[nt]);
        }
    }

    const float qscale = 0.17677669529663689f;
    const float kscale = 1.0f / (float)L;
    #pragma unroll
    for (int mt = 0; mt < 2; mt++) {
        #pragma unroll
        for (int hf = 0; hf < 2; hf++) {
            int m = m0 + wm*32 + mt*16 + lrow + hf*8;
            int n = m / L, i = m - n*L;
            #pragma unroll
            for (int nt = 0; nt < 8; nt++) {
                int c = wn*64 + nt*8 + 2*lq;
                float v0 = acc[mt][nt][hf*2+0];
                float v1 = acc[mt][nt][hf*2+1];
                if (which == 0) {
                    int h = c >> 5, d = c & 31;
                    __nv_bfloat162 qv;
                    qv.x = __float2bfloat16(v0*qscale);
                    qv.y = __float2bfloat16(v1*qscale);
                    *(__nv_bfloat162*)(g_qb + ((size_t)(h*L+n)*L + i)*DH + d) = qv;
                } else if (which == 1) {
                    int h = c >> 5, d = c & 31;
                    __nv_bfloat162 kv;
                    kv.x = __float2bfloat16(v0*kscale);
                    kv.y = __float2bfloat16(v1*kscale);
                    *(__nv_bfloat162*)(g_kb + ((size_t)(h*L+n)*L + i)*DH + d) = kv;
                } else if (which == 2) {
                    int h = c >> 5, d = c & 31;     // m = n*L + j here (j = i)
                    *(float2*)(g_vT + ((size_t)(h*L+i)*L + n)*DH + d) =
                        make_float2(tf32r(v0), tf32r(v1));
                } else {
                    v0 = 1.0f/(1.0f + expf(-(v0 + bg[c  ])));
                    v1 = 1.0f/(1.0f + expf(-(v1 + bg[c+1])));
                    *(float2*)(g_gate + (size_t)m*DP + c) = make_float2(v0, v1);
                }
            }
        }
    }
}

// ---------------- kernel 4: QK logits, bf16 MMA, split-K, cp.async ----------------
__global__ __launch_bounds__(256) void k_qk()
{
    __shared__ __align__(16) __nv_bfloat16 Qs[2][128][40];
    __shared__ __align__(16) __nv_bfloat16 Ks[2][128][40];
    int i0 = blockIdx.x * 128, j0 = blockIdx.y * 128;
    int h = blockIdx.z & 3, s = blockIdx.z >> 2;
    int tid = threadIdx.x;
    int w = tid >> 5, lane = tid & 31;
    int wm = w >> 1, wn = w & 1;
    int lrow = lane >> 2, lq = lane & 3;
    const __nv_bfloat16* Qg = g_qb + (size_t)h*L*L*DH;
    const __nv_bfloat16* Kg = g_kb + (size_t)h*L*L*DH;

    auto load = [&](int st, int n) {
        #pragma unroll
        for (int it = 0; it < 2; it++) {
            int cid = tid + it*256;
            int row = cid >> 2, part = cid & 3;
            cpa16(&Qs[st][row][part*8], Qg + ((size_t)n*L + i0 + row)*DH + part*8);
        }
        #pragma unroll
        for (int it = 0; it < 2; it++) {
            int cid = tid + it*256;
            int row = cid >> 2, part = cid & 3;
            cpa16(&Ks[st][row][part*8], Kg + ((size_t)n*L + j0 + row)*DH + part*8);
        }
    };

    float acc[2][8][4];
    #pragma unroll
    for (int mt = 0; mt < 2; mt++)
        #pragma unroll
        for (int nt = 0; nt < 8; nt++)
            #pragma unroll
            for (int r = 0; r < 4; r++) acc[mt][nt][r] = 0.f;

    load(0, s*NSPL); CPA_COMMIT;
    for (int nn = 0; nn < NSPL; nn++) {
        CPA_WAIT0; __syncthreads();
        if (nn+1 < NSPL) { load((nn+1)&1, s*NSPL + nn + 1); CPA_COMMIT; }
        int st = nn & 1;
        #pragma unroll
        for (int ks = 0; ks < 2; ks++) {
            int cb = ks*16;
            unsigned a[2][4], b[8][2];
            #pragma unroll
            for (int mt = 0; mt < 2; mt++) {
                int mr = wm*32 + mt*16 + lrow;
                a[mt][0] = *(const unsigned*)&Qs[st][mr  ][cb+2*lq];
                a[mt][1] = *(const unsigned*)&Qs[st][mr+8][cb+2*lq];
                a[mt][2] = *(const unsigned*)&Qs[st][mr  ][cb+2*lq+8];
                a[mt][3] = *(const unsigned*)&Qs[st][mr+8][cb+2*lq+8];
            }
            #pragma unroll
            for (int nt = 0; nt < 8; nt++) {
                int nb = wn*64 + nt*8 + lrow;
                b[nt][0] = *(const unsigned*)&Ks[st][nb][cb+2*lq];
                b[nt][1] = *(const unsigned*)&Ks[st][nb][cb+2*lq+8];
            }
            #pragma unroll
            for (int mt = 0; mt < 2; mt++)
                #pragma unroll
                for (int nt = 0; nt < 8; nt++)
                    mma16(acc[mt][nt], a[mt], b[nt]);
        }
    }
    float* dst = g_qkp + (size_t)(s*NH + h)*LL;
    #pragma unroll
    for (int mt = 0; mt < 2; mt++)
        #pragma unroll
        for (int hf = 0; hf < 2; hf++) {
            int i = i0 + wm*32 + mt*16 + lrow + hf*8;
            #pragma unroll
            for (int nt = 0; nt < 8; nt++) {
                int j = j0 + wn*64 + nt*8 + 2*lq;
                *(float2*)(dst + (size_t)i*L + j) =
                    make_float2(acc[mt][nt][hf*2], acc[mt][nt][hf*2+1]);
            }
        }
}

// ---------------- kernel 5: softmax (split-K reduce + bias, tf32-rounded store) ----------------
__global__ __launch_bounds__(128) void k_softmax()
{
    __shared__ float redm[4], reds[4];
    int i = blockIdx.x, h = blockIdx.y;
    int tid = threadIdx.x;
    float v[3];
    float mx = -1e30f;
    #pragma unroll
    for (int r = 0; r < 3; r++) {
        int j = tid + r*128;
        float a = g_battn[((size_t)i*L + j)*NH + h];
        #pragma unroll
        for (int s = 0; s < SPLIT; s++)
            a += g_qkp[(size_t)(s*NH + h)*LL + (size_t)i*L + j];
        v[r] = a;
        mx = fmaxf(mx, a);
    }
    #pragma unroll
    for (int o = 16; o; o >>= 1) mx = fmaxf(mx, __shfl_xor_sync(0xffffffffu, mx, o));
    if ((tid & 31) == 0) redm[tid >> 5] = mx;
    __syncthreads();
    mx = fmaxf(fmaxf(redm[0], redm[1]), fmaxf(redm[2], redm[3]));
    float se = 0.f;
    #pragma unroll
    for (int r = 0; r < 3; r++) { v[r] = expf(v[r] - mx); se += v[r]; }
    #pragma unroll
    for (int o = 16; o; o >>= 1) se += __shfl_xor_sync(0xffffffffu, se, o);
    if ((tid & 31) == 0) reds[tid >> 5] = se;
    __syncthreads();
    se = reds[0] + reds[1] + reds[2] + reds[3];
    float inv = 1.0f / se;
    float* dst = g_attn + (size_t)h*LL + (size_t)i*L;
    #pragma unroll
    for (int r = 0; r < 3; r++) dst[tid + r*128] = tf32r(v[r] * inv);
}

// ---------------- kernel 6: AV per-head GEMM, tf32 MMA, cp.async ----------------
__global__ __launch_bounds__(256) void k_o()
{
    extern __shared__ float sm[];
    float (*As)[128][PADA] = (float(*)[128][PADA])sm;              // 2 stages
    float (*Bs)[32][PADB]  = (float(*)[32][PADB])(sm + 2*128*PADA);
    int i0  = blockIdx.x * 128;
    int nd0 = blockIdx.y * 128;
    int h   = blockIdx.z;
    int tid = threadIdx.x;
    int w = tid >> 5, lane = tid & 31;
    int wm = w >> 1, wn = w & 1;
    int lrow = lane >> 2, lq = lane & 3;
    const float* A = g_attn + (size_t)h*LL;
    const float* B = g_vT + (size_t)h*L*L*DH;

    auto load = [&](int st, int k0) {
        #pragma unroll
        for (int it = 0; it < 4; it++) {
            int cid = tid + it*256;
            int row = cid >> 3, part = cid & 7;
            cpa16(&As[st][row][part*4], A + (size_t)(i0+row)*L + k0 + part*4);
        }
        #pragma unroll
        for (int it = 0; it < 4; it++) {
            int cid = tid + it*256;
            int row = cid >> 5, part = cid & 31;
            cpa16(&Bs[st][row][part*4], B + (size_t)(k0+row)*(L*DH) + nd0 + part*4);
        }
    };

    float acc[2][8][4];
    #pragma unroll
    for (int mt = 0; mt < 2; mt++)
        #pragma unroll
        for (int nt = 0; nt < 8; nt++)
            #pragma unroll
            for (int r = 0; r < 4; r++) acc[mt][nt][r] = 0.f;

    load(0, 0); CPA_COMMIT;
    for (int kt = 0; kt < 12; kt++) {
        CPA_WAIT0; __syncthreads();
        if (kt < 11) { load((kt+1)&1, (kt+1)*32); CPA_COMMIT; }
        int st = kt & 1;
        #pragma unroll
        for (int ks = 0; ks < 4; ks++) {
            int kk = ks*8;
            float a[2][4], b[8][2];
            #pragma unroll
            for (int mt = 0; mt < 2; mt++) {
                int mr = wm*32 + mt*16 + lrow;
                a[mt][0] = As[st][mr  ][kk+lq];
                a[mt][1] = As[st][mr+8][kk+lq];
                a[mt][2] = As[st][mr  ][kk+lq+4];
                a[mt][3] = As[st][mr+8][kk+lq+4];
            }
            #pragma unroll
            for (int nt = 0; nt < 8; nt++) {
                int nb = wn*64 + nt*8 + lrow;
                b[nt][0] = Bs[st][kk+lq  ][nb];
                b[nt][1] = Bs[st][kk+lq+4][nb];
            }
            #pragma unroll
            for (int mt = 0; mt < 2; mt++)
                #pragma unroll
                for (int nt = 0; nt < 8; nt++)
                    mma8(acc[mt][nt], a[mt], b[nt]);
        }
    }
    #pragma unroll
    for (int mt = 0; mt < 2; mt++)
        #pragma unroll
        for (int hf = 0; hf < 2; hf++) {
            int i = i0 + wm*32 + mt*16 + lrow + hf*8;
            #pragma unroll
            for (int nt = 0; nt < 8; nt++) {
                int nd = nd0 + wn*64 + nt*8 + 2*lq;
                int n = nd >> 5, d = nd & 31;
                *(float2*)(g_o + (size_t)(n*L + i)*DP + h*DH + d) =
                    make_float2(acc[mt][nt][hf*2], acc[mt][nt][hf*2+1]);
            }
        }
}

// ---------------- kernel 7: out = (gate*o) @ Wout + bout ----------------
__global__ __launch_bounds__(256) void k_out(const float* __restrict__ Wout,
                                             const float* __restrict__ bout,
                                             float* __restrict__ out)
{
    __shared__ float As[128][36];
    __shared__ float Bs[32][132];
    int m0 = blockIdx.x * 128;
    int n  = m0 / L;
    int ib = m0 % L;
    int tid = threadIdx.x;
    int w = tid >> 5, lane = tid & 31;
    int wm = w >> 1, wn = w & 1;
    int lrow = lane >> 2, lq = lane & 3;
    float acc[2][8][4];
    #pragma unroll
    for (int mt = 0; mt < 2; mt++)
        #pragma unroll
        for (int nt = 0; nt < 8; nt++)
            #pragma unroll
            for (int r = 0; r < 4; r++) acc[mt][nt][r] = 0.f;

    for (int k0 = 0; k0 < DP; k0 += 32) {
        #pragma unroll
        for (int it = 0; it < 4; it++) {
            int idx4 = tid + it*256;
            int row = idx4 >> 3, col = (idx4 & 7) * 4;
            size_t base = (size_t)(m0+row)*DP + k0 + col;
            float4 ov = *(const float4*)(g_o + base);
            float4 gv = *(const float4*)(g_gate + base);
            *(float4*)&As[row][col] =
                make_float4(tf32r(ov.x*gv.x), tf32r(ov.y*gv.y),
                            tf32r(ov.z*gv.z), tf32r(ov.w*gv.w));
        }
        #pragma unroll
        for (int it = 0; it < 4; it++) {
            int idx4 = tid + it*256;
            int row = idx4 >> 5, col = (idx4 & 31) * 4;
            float4 v = *(const float4*)(Wout + (size_t)(k0+row)*DP + col);
            *(float4*)&Bs[row][col] =
                make_float4(tf32r(v.x), tf32r(v.y), tf32r(v.z), tf32r(v.w));
        }
        __syncthreads();
        #pragma unroll
        for (int ks = 0; ks < 4; ks++) {
            int kk = ks*8;
            float a[2][4], b[8][2];
            #pragma unroll
            for (int mt = 0; mt < 2; mt++) {
                int mr = wm*32 + mt*16 + lrow;
                a[mt][0] = As[mr  ][kk+lq];
                a[mt][1] = As[mr+8][kk+lq];
                a[mt][2] = As[mr  ][kk+lq+4];
                a[mt][3] = As[mr+8][kk+lq+4];
            }
            #pragma unroll
            for (int nt = 0; nt < 8; nt++) {
                int nb = wn*64 + nt*8 + lrow;
                b[nt][0] = Bs[kk+lq  ][nb];
                b[nt][1] = Bs[kk+lq+4][nb];
            }
            #pragma unroll
            for (int mt = 0; mt < 2; mt++)
                #pragma unroll
                for (int nt = 0; nt < 8; nt++)
                    mma8(acc[mt][nt], a[mt], b[nt]);
        }
        __syncthreads();
    }
    #pragma unroll
    for (int mt = 0; mt < 2; mt++)
        #pragma unroll
        for (int hf = 0; hf < 2; hf++) {
            int i = ib + wm*32 + mt*16 + lrow + hf*8;
            size_t row = (size_t)i*L + n;
            #pragma unroll
            for (int nt = 0; nt < 8; nt++) {
                int c = wn*64 + nt*8 + 2*lq;
                *(float2*)(out + row*DP + c) =
                    make_float2(acc[mt][nt][hf*2]   + bout[c],
                                acc[mt][nt][hf*2+1] + bout[c+1]);
            }
        }
}

// ---------------- launch ----------------
extern "C" void kernel_launch(void* const* d_in, const int* in_sizes, int n_in,
                              void* d_out, int out_size)
{
    const float* pair    = (const float*)d_in[0];
    const float* bias    = (const float*)d_in[1];
    const float* gamma_p = (const float*)d_in[2];
    const float* beta_p  = (const float*)d_in[3];
    const float* gamma_b = (const float*)d_in[4];
    const float* beta_b  = (const float*)d_in[5];
    const float* Wq      = (const float*)d_in[6];
    const float* Wk      = (const float*)d_in[7];
    const float* Wv      = (const float*)d_in[8];
    const float* Wb      = (const float*)d_in[9];
    const float* Wg      = (const float*)d_in[10];
    const float* bg      = (const float*)d_in[11];
    const float* Wout    = (const float*)d_in[12];
    const float* bout    = (const float*)d_in[13];
    float* out = (float*)d_out;

    const int smProj = (2*128*PADA + 128*PADB) * 4;      // 106496 B
    const int smO    = (2*128*PADA + 2*32*PADB) * 4;     // 71680 B
    cudaFuncSetAttribute(k_proj, cudaFuncAttributeMaxDynamicSharedMemorySize, smProj);
    cudaFuncSetAttribute(k_o,    cudaFuncAttributeMaxDynamicSharedMemorySize, smO);

    k_ln_pair <<<LL/8, 256>>>(pair, gamma_p, beta_p);
    k_bias    <<<LL/8, 256>>>(bias, gamma_b, beta_b, Wb);
    k_proj    <<<dim3(LL/128, 4), 256, smProj>>>(Wq, Wk, Wv, Wg, bg);
    k_qk      <<<dim3(3, 3, NH*SPLIT), 256>>>();
    k_softmax <<<dim3(L, NH), 128>>>();
    k_o       <<<dim3(3, (L*DH)/128, NH), 256, smO>>>();
    k_out     <<<LL/128, 256>>>(Wout, bout, out);
}

// round 4
// speedup vs baseline: 3.4219x; 1.0165x over previous
#include <cuda_runtime.h>
#include <cuda_bf16.h>
#include <math.h>

#define L    384
#define DP   128
#define NH   4
#define DH   32
#define LL   (L*L)            // 147456
#define SPLIT 16
#define NSPL  (L/SPLIT)       // 24

// ---------------- scratch ----------------
__device__ __nv_bfloat16 g_qb[NH*LL*DH];     // q bf16: ((h*L+n)*L+i)*32+d
__device__ __nv_bfloat16 g_kb[NH*LL*DH];     // k bf16: ((h*L+n)*L+j)*32+d
__device__ float g_vT  [NH*LL*DH];           // v tf32-rounded: ((h*L+j)*L+n)*32+d
__device__ float g_gate[LL*DP];
__device__ float g_o   [LL*DP];              // gated + tf32-rounded, row n*L+i
__device__ float g_attn[NH*LL];              // softmax probs, tf32-rounded
__device__ float g_battn[NH*LL];             // [h][i][j]
__device__ float g_qkp [SPLIT*NH*LL];        // qk partials [s][h][i][j]
__device__ float g_w4  [4*DP*DP];            // tf32-rounded Wq|Wk|Wv|Wg
__device__ float g_wout[DP*DP];              // tf32-rounded Wout

// ---------------- helpers ----------------
__device__ __forceinline__ float tf32r(float x) {
    float y; asm("cvt.rna.tf32.f32 %0, %1;" : "=f"(y) : "f"(x)); return y;
}
__device__ __forceinline__ void cpa16(void* dst, const void* src) {
    unsigned d = (unsigned)__cvta_generic_to_shared(dst);
    asm volatile("cp.async.cg.shared.global [%0], [%1], 16;\n" :: "r"(d), "l"(src));
}
#define CPA_COMMIT asm volatile("cp.async.commit_group;\n" ::: "memory")
#define CPA_WAIT0  asm volatile("cp.async.wait_group 0;\n" ::: "memory")

__device__ __forceinline__ void mma8(float c[4], const float a[4], const float b[2]) {
    asm volatile(
        "mma.sync.aligned.m16n8k8.row.col.f32.tf32.tf32.f32 "
        "{%0,%1,%2,%3},{%4,%5,%6,%7},{%8,%9},{%0,%1,%2,%3};\n"
        : "+f"(c[0]), "+f"(c[1]), "+f"(c[2]), "+f"(c[3])
        : "r"(__float_as_uint(a[0])), "r"(__float_as_uint(a[1])),
          "r"(__float_as_uint(a[2])), "r"(__float_as_uint(a[3])),
          "r"(__float_as_uint(b[0])), "r"(__float_as_uint(b[1])));
}
__device__ __forceinline__ void mma16(float c[4], const unsigned a[4], const unsigned b[2]) {
    asm volatile(
        "mma.sync.aligned.m16n8k16.row.col.f32.bf16.bf16.f32 "
        "{%0,%1,%2,%3},{%4,%5,%6,%7},{%8,%9},{%0,%1,%2,%3};\n"
        : "+f"(c[0]), "+f"(c[1]), "+f"(c[2]), "+f"(c[3])
        : "r"(a[0]), "r"(a[1]), "r"(a[2]), "r"(a[3]), "r"(b[0]), "r"(b[1]));
}

// ---------------- kernel 0: pre-round weights to tf32 ----------------
__global__ __launch_bounds__(256) void k_prep(const float* __restrict__ Wq,
                                              const float* __restrict__ Wk,
                                              const float* __restrict__ Wv,
                                              const float* __restrict__ Wg,
                                              const float* __restrict__ Wout)
{
    int id = blockIdx.x * 256 + threadIdx.x;     // 81920 total
    if (id < 4*DP*DP) {
        int which = id >> 14, rem = id & (DP*DP - 1);
        const float* W = (which==0) ? Wq : (which==1) ? Wk : (which==2) ? Wv : Wg;
        g_w4[id] = tf32r(W[rem]);
    } else {
        int rem = id - 4*DP*DP;
        g_wout[rem] = tf32r(Wout[rem]);
    }
}

// ---------------- kernel 2: bias path ----------------
__global__ __launch_bounds__(256) void k_bias(const float* __restrict__ bias,
                                              const float* __restrict__ gamma,
                                              const float* __restrict__ beta,
                                              const float* __restrict__ Wb)
{
    int warp = (blockIdx.x * blockDim.x + threadIdx.x) >> 5;
    int lane = threadIdx.x & 31;
    if (warp >= LL) return;
    int i = warp / L, j = warp % L;
    float4 x = ((const float4*)(bias + (size_t)(j*L + i) * DP))[lane];
    float s  = x.x + x.y + x.z + x.w;
    float ss = x.x*x.x + x.y*x.y + x.z*x.z + x.w*x.w;
    #pragma unroll
    for (int o = 16; o; o >>= 1) {
        s  += __shfl_xor_sync(0xffffffffu, s,  o);
        ss += __shfl_xor_sync(0xffffffffu, ss, o);
    }
    float mean = s * (1.0f/DP);
    float var  = ss * (1.0f/DP) - mean*mean;
    float inv  = rsqrtf(var + 1e-5f);
    float4 g = ((const float4*)gamma)[lane];
    float4 b = ((const float4*)beta )[lane];
    float y[4];
    y[0] = (x.x - mean)*inv*g.x + b.x;
    y[1] = (x.y - mean)*inv*g.y + b.y;
    y[2] = (x.z - mean)*inv*g.z + b.z;
    y[3] = (x.w - mean)*inv*g.w + b.w;
    float acc[NH] = {0.f, 0.f, 0.f, 0.f};
    #pragma unroll
    for (int t = 0; t < 4; t++) {
        int c = lane*4 + t;
        #pragma unroll
        for (int h = 0; h < NH; h++)
            acc[h] += y[t] * Wb[c*NH + h];
    }
    #pragma unroll
    for (int h = 0; h < NH; h++)
        #pragma unroll
        for (int o = 16; o; o >>= 1)
            acc[h] += __shfl_xor_sync(0xffffffffu, acc[h], o);
    if (lane == 0) {
        #pragma unroll
        for (int h = 0; h < NH; h++)
            g_battn[(size_t)h*LL + warp] = acc[h];
    }
}

// ---------------- kernel 3: fused LN + 4 projections ----------------
// A (128 rows of LN'd pair_t, full K=128) resident in smem; loop 4 weights.
#define APAD 132
#define WPAD 136
__global__ __launch_bounds__(256) void k_projf(const float* __restrict__ pair,
                                               const float* __restrict__ gamma,
                                               const float* __restrict__ beta,
                                               const float* __restrict__ bg)
{
    extern __shared__ float sm[];
    float (*As)[APAD]      = (float(*)[APAD])sm;                    // [128][APAD]
    float (*Bs)[128][WPAD] = (float(*)[128][WPAD])(sm + 128*APAD);  // [2][128][WPAD]
    int m0 = blockIdx.x * 128;
    int n  = m0 / L;               // constant (128 | 384)
    int i0 = m0 % L;
    int tid = threadIdx.x;
    int w = tid >> 5, lane = tid & 31;
    int wm = w >> 1, wn = w & 1;
    int lrow = lane >> 2, lq = lane & 3;

    // async load raw pair rows: row p = m0+r  ->  pair[(i0+r)*L + n]
    #pragma unroll
    for (int it = 0; it < 16; it++) {
        int cid = tid + it*256;                 // 4096 16B chunks
        int row = cid >> 5, part = cid & 31;
        cpa16(&As[row][part*4], pair + ((size_t)(i0+row)*L + n)*DP + part*4);
    }
    CPA_COMMIT;
    // async load W0
    #pragma unroll
    for (int it = 0; it < 16; it++) {
        int cid = tid + it*256;
        int row = cid >> 5, part = cid & 31;
        cpa16(&Bs[0][row][part*4], g_w4 + (size_t)row*DP + part*4);
    }
    CPA_COMMIT;
    CPA_WAIT0; __syncthreads();

    // LN in smem: warp w handles rows w*16 .. w*16+15
    {
        float4 gm = ((const float4*)gamma)[lane];
        float4 bt = ((const float4*)beta )[lane];
        for (int r = 0; r < 16; r++) {
            int row = w*16 + r;
            float4 x = *(float4*)&As[row][lane*4];
            float s  = x.x + x.y + x.z + x.w;
            float ss = x.x*x.x + x.y*x.y + x.z*x.z + x.w*x.w;
            #pragma unroll
            for (int o = 16; o; o >>= 1) {
                s  += __shfl_xor_sync(0xffffffffu, s,  o);
                ss += __shfl_xor_sync(0xffffffffu, ss, o);
            }
            float mean = s * (1.0f/DP);
            float var  = ss * (1.0f/DP) - mean*mean;
            float inv  = rsqrtf(var + 1e-5f);
            float4 y;
            y.x = tf32r((x.x - mean)*inv*gm.x + bt.x);
            y.y = tf32r((x.y - mean)*inv*gm.y + bt.y);
            y.z = tf32r((x.z - mean)*inv*gm.z + bt.z);
            y.w = tf32r((x.w - mean)*inv*gm.w + bt.w);
            *(float4*)&As[row][lane*4] = y;
        }
    }
    __syncthreads();

    const float qscale = 0.17677669529663689f;
    const float kscale = 1.0f / (float)L;

    for (int which = 0; which < 4; which++) {
        int buf = which & 1;
        if (which < 3) {
            #pragma unroll
            for (int it = 0; it < 16; it++) {
                int cid = tid + it*256;
                int row = cid >> 5, part = cid & 31;
                cpa16(&Bs[buf^1][row][part*4],
                      g_w4 + (size_t)(which+1)*DP*DP + (size_t)row*DP + part*4);
            }
            CPA_COMMIT;
        }

        float acc[2][8][4];
        #pragma unroll
        for (int mt = 0; mt < 2; mt++)
            #pragma unroll
            for (int nt = 0; nt < 8; nt++)
                #pragma unroll
                for (int r = 0; r < 4; r++) acc[mt][nt][r] = 0.f;

        #pragma unroll 4
        for (int ks = 0; ks < 16; ks++) {
            int kk = ks*8;
            float a[2][4], b[8][2];
            #pragma unroll
            for (int mt = 0; mt < 2; mt++) {
                int mr = wm*32 + mt*16 + lrow;
                a[mt][0] = As[mr  ][kk+lq];
                a[mt][1] = As[mr+8][kk+lq];
                a[mt][2] = As[mr  ][kk+lq+4];
                a[mt][3] = As[mr+8][kk+lq+4];
            }
            #pragma unroll
            for (int nt = 0; nt < 8; nt++) {
                int nb = wn*64 + nt*8 + lrow;
                b[nt][0] = Bs[buf][kk+lq  ][nb];
                b[nt][1] = Bs[buf][kk+lq+4][nb];
            }
            #pragma unroll
            for (int mt = 0; mt < 2; mt++)
                #pragma unroll
                for (int nt = 0; nt < 8; nt++)
                    mma8(acc[mt][nt], a[mt], b[nt]);
        }

        // epilogue
        #pragma unroll
        for (int mt = 0; mt < 2; mt++) {
            #pragma unroll
            for (int hf = 0; hf < 2; hf++) {
                int i = i0 + wm*32 + mt*16 + lrow + hf*8;
                #pragma unroll
                for (int nt = 0; nt < 8; nt++) {
                    int c = wn*64 + nt*8 + 2*lq;
                    float v0 = acc[mt][nt][hf*2+0];
                    float v1 = acc[mt][nt][hf*2+1];
                    if (which == 0) {
                        int h = c >> 5, d = c & 31;
                        __nv_bfloat162 qv;
                        qv.x = __float2bfloat16(v0*qscale);
                        qv.y = __float2bfloat16(v1*qscale);
                        *(__nv_bfloat162*)(g_qb + ((size_t)(h*L+n)*L + i)*DH + d) = qv;
                    } else if (which == 1) {
                        int h = c >> 5, d = c & 31;
                        __nv_bfloat162 kv;
                        kv.x = __float2bfloat16(v0*kscale);
                        kv.y = __float2bfloat16(v1*kscale);
                        *(__nv_bfloat162*)(g_kb + ((size_t)(h*L+n)*L + i)*DH + d) = kv;
                    } else if (which == 2) {
                        int h = c >> 5, d = c & 31;
                        *(float2*)(g_vT + ((size_t)(h*L+i)*L + n)*DH + d) =
                            make_float2(tf32r(v0), tf32r(v1));
                    } else {
                        v0 = 1.0f/(1.0f + expf(-(v0 + bg[c  ])));
                        v1 = 1.0f/(1.0f + expf(-(v1 + bg[c+1])));
                        *(float2*)(g_gate + ((size_t)(n*L+i))*DP + c) = make_float2(v0, v1);
                    }
                }
            }
        }
        if (which < 3) { CPA_WAIT0; __syncthreads(); }
    }
}

// ---------------- kernel 4: QK logits, bf16 MMA, split-K, cp.async ----------------
__global__ __launch_bounds__(256) void k_qk()
{
    __shared__ __align__(16) __nv_bfloat16 Qs[2][128][40];
    __shared__ __align__(16) __nv_bfloat16 Ks[2][128][40];
    int i0 = blockIdx.x * 128, j0 = blockIdx.y * 128;
    int h = blockIdx.z & 3, s = blockIdx.z >> 2;
    int tid = threadIdx.x;
    int w = tid >> 5, lane = tid & 31;
    int wm = w >> 1, wn = w & 1;
    int lrow = lane >> 2, lq = lane & 3;
    const __nv_bfloat16* Qg = g_qb + (size_t)h*L*L*DH;
    const __nv_bfloat16* Kg = g_kb + (size_t)h*L*L*DH;

    auto load = [&](int st, int n) {
        #pragma unroll
        for (int it = 0; it < 2; it++) {
            int cid = tid + it*256;
            int row = cid >> 2, part = cid & 3;
            cpa16(&Qs[st][row][part*8], Qg + ((size_t)n*L + i0 + row)*DH + part*8);
        }
        #pragma unroll
        for (int it = 0; it < 2; it++) {
            int cid = tid + it*256;
            int row = cid >> 2, part = cid & 3;
            cpa16(&Ks[st][row][part*8], Kg + ((size_t)n*L + j0 + row)*DH + part*8);
        }
    };

    float acc[2][8][4];
    #pragma unroll
    for (int mt = 0; mt < 2; mt++)
        #pragma unroll
        for (int nt = 0; nt < 8; nt++)
            #pragma unroll
            for (int r = 0; r < 4; r++) acc[mt][nt][r] = 0.f;

    load(0, s*NSPL); CPA_COMMIT;
    for (int nn = 0; nn < NSPL; nn++) {
        CPA_WAIT0; __syncthreads();
        if (nn+1 < NSPL) { load((nn+1)&1, s*NSPL + nn + 1); CPA_COMMIT; }
        int st = nn & 1;
        #pragma unroll
        for (int ks = 0; ks < 2; ks++) {
            int cb = ks*16;
            unsigned a[2][4], b[8][2];
            #pragma unroll
            for (int mt = 0; mt < 2; mt++) {
                int mr = wm*32 + mt*16 + lrow;
                a[mt][0] = *(const unsigned*)&Qs[st][mr  ][cb+2*lq];
                a[mt][1] = *(const unsigned*)&Qs[st][mr+8][cb+2*lq];
                a[mt][2] = *(const unsigned*)&Qs[st][mr  ][cb+2*lq+8];
                a[mt][3] = *(const unsigned*)&Qs[st][mr+8][cb+2*lq+8];
            }
            #pragma unroll
            for (int nt = 0; nt < 8; nt++) {
                int nb = wn*64 + nt*8 + lrow;
                b[nt][0] = *(const unsigned*)&Ks[st][nb][cb+2*lq];
                b[nt][1] = *(const unsigned*)&Ks[st][nb][cb+2*lq+8];
            }
            #pragma unroll
            for (int mt = 0; mt < 2; mt++)
                #pragma unroll
                for (int nt = 0; nt < 8; nt++)
                    mma16(acc[mt][nt], a[mt], b[nt]);
        }
    }
    float* dst = g_qkp + (size_t)(s*NH + h)*LL;
    #pragma unroll
    for (int mt = 0; mt < 2; mt++)
        #pragma unroll
        for (int hf = 0; hf < 2; hf++) {
            int i = i0 + wm*32 + mt*16 + lrow + hf*8;
            #pragma unroll
            for (int nt = 0; nt < 8; nt++) {
                int j = j0 + wn*64 + nt*8 + 2*lq;
                *(float2*)(dst + (size_t)i*L + j) =
                    make_float2(acc[mt][nt][hf*2], acc[mt][nt][hf*2+1]);
            }
        }
}

// ---------------- kernel 5: softmax ----------------
__global__ __launch_bounds__(128) void k_softmax()
{
    __shared__ float redm[4], reds[4];
    int i = blockIdx.x, h = blockIdx.y;
    int tid = threadIdx.x;
    float v[3];
    float mx = -1e30f;
    #pragma unroll
    for (int r = 0; r < 3; r++) {
        int j = tid + r*128;
        float a = g_battn[(size_t)h*LL + (size_t)i*L + j];
        #pragma unroll
        for (int s = 0; s < SPLIT; s++)
            a += g_qkp[(size_t)(s*NH + h)*LL + (size_t)i*L + j];
        v[r] = a;
        mx = fmaxf(mx, a);
    }
    #pragma unroll
    for (int o = 16; o; o >>= 1) mx = fmaxf(mx, __shfl_xor_sync(0xffffffffu, mx, o));
    if ((tid & 31) == 0) redm[tid >> 5] = mx;
    __syncthreads();
    mx = fmaxf(fmaxf(redm[0], redm[1]), fmaxf(redm[2], redm[3]));
    float se = 0.f;
    #pragma unroll
    for (int r = 0; r < 3; r++) { v[r] = expf(v[r] - mx); se += v[r]; }
    #pragma unroll
    for (int o = 16; o; o >>= 1) se += __shfl_xor_sync(0xffffffffu, se, o);
    if ((tid & 31) == 0) reds[tid >> 5] = se;
    __syncthreads();
    se = reds[0] + reds[1] + reds[2] + reds[3];
    float inv = 1.0f / se;
    float* dst = g_attn + (size_t)h*LL + (size_t)i*L;
    #pragma unroll
    for (int r = 0; r < 3; r++) dst[tid + r*128] = tf32r(v[r] * inv);
}

// ---------------- kernel 6: AV per-head GEMM + gate epilogue ----------------
#define PADA 36
#define PADB 136
__global__ __launch_bounds__(256) void k_o()
{
    extern __shared__ float sm[];
    float (*As)[128][PADA] = (float(*)[128][PADA])sm;
    float (*Bs)[32][PADB]  = (float(*)[32][PADB])(sm + 2*128*PADA);
    int i0  = blockIdx.x * 128;
    int nd0 = blockIdx.y * 128;
    int h   = blockIdx.z;
    int tid = threadIdx.x;
    int w = tid >> 5, lane = tid & 31;
    int wm = w >> 1, wn = w & 1;
    int lrow = lane >> 2, lq = lane & 3;
    const float* A = g_attn + (size_t)h*LL;
    const float* B = g_vT + (size_t)h*L*L*DH;

    auto load = [&](int st, int k0) {
        #pragma unroll
        for (int it = 0; it < 4; it++) {
            int cid = tid + it*256;
            int row = cid >> 3, part = cid & 7;
            cpa16(&As[st][row][part*4], A + (size_t)(i0+row)*L + k0 + part*4);
        }
        #pragma unroll
        for (int it = 0; it < 4; it++) {
            int cid = tid + it*256;
            int row = cid >> 5, part = cid & 31;
            cpa16(&Bs[st][row][part*4], B + (size_t)(k0+row)*(L*DH) + nd0 + part*4);
        }
    };

    float acc[2][8][4];
    #pragma unroll
    for (int mt = 0; mt < 2; mt++)
        #pragma unroll
        for (int nt = 0; nt < 8; nt++)
            #pragma unroll
            for (int r = 0; r < 4; r++) acc[mt][nt][r] = 0.f;

    load(0, 0); CPA_COMMIT;
    for (int kt = 0; kt < 12; kt++) {
        CPA_WAIT0; __syncthreads();
        if (kt < 11) { load((kt+1)&1, (kt+1)*32); CPA_COMMIT; }
        int st = kt & 1;
        #pragma unroll
        for (int ks = 0; ks < 4; ks++) {
            int kk = ks*8;
            float a[2][4], b[8][2];
            #pragma unroll
            for (int mt = 0; mt < 2; mt++) {
                int mr = wm*32 + mt*16 + lrow;
                a[mt][0] = As[st][mr  ][kk+lq];
                a[mt][1] = As[st][mr+8][kk+lq];
                a[mt][2] = As[st][mr  ][kk+lq+4];
                a[mt][3] = As[st][mr+8][kk+lq+4];
            }
            #pragma unroll
            for (int nt = 0; nt < 8; nt++) {
                int nb = wn*64 + nt*8 + lrow;
                b[nt][0] = Bs[st][kk+lq  ][nb];
                b[nt][1] = Bs[st][kk+lq+4][nb];
            }
            #pragma unroll
            for (int mt = 0; mt < 2; mt++)
                #pragma unroll
                for (int nt = 0; nt < 8; nt++)
                    mma8(acc[mt][nt], a[mt], b[nt]);
        }
    }
    #pragma unroll
    for (int mt = 0; mt < 2; mt++)
        #pragma unroll
        for (int hf = 0; hf < 2; hf++) {
            int i = i0 + wm*32 + mt*16 + lrow + hf*8;
            #pragma unroll
            for (int nt = 0; nt < 8; nt++) {
                int nd = nd0 + wn*64 + nt*8 + 2*lq;
                int n = nd >> 5, d = nd & 31;
                size_t off = (size_t)(n*L + i)*DP + h*DH + d;
                float2 gv = *(const float2*)(g_gate + off);
                *(float2*)(g_o + off) =
                    make_float2(tf32r(acc[mt][nt][hf*2]  * gv.x),
                                tf32r(acc[mt][nt][hf*2+1]* gv.y));
            }
        }
}

// ---------------- kernel 7: out = g_o @ Wout + bout ----------------
__global__ __launch_bounds__(256) void k_out(const float* __restrict__ bout,
                                             float* __restrict__ out)
{
    extern __shared__ float sm[];
    float (*As)[128][PADA] = (float(*)[128][PADA])sm;           // 2 stages, 128x32
    float (*Bs)[PADB]      = (float(*)[PADB])(sm + 2*128*PADA); // [128][PADB]
    int m0 = blockIdx.x * 128;
    int n  = m0 / L;
    int ib = m0 % L;
    int tid = threadIdx.x;
    int w = tid >> 5, lane = tid & 31;
    int wm = w >> 1, wn = w & 1;
    int lrow = lane >> 2, lq = lane & 3;

    auto loadA = [&](int st, int k0) {
        #pragma unroll
        for (int it = 0; it < 4; it++) {
            int cid = tid + it*256;
            int row = cid >> 3, part = cid & 7;
            cpa16(&As[st][row][part*4], g_o + (size_t)(m0+row)*DP + k0 + part*4);
        }
    };
    // resident pre-rounded Wout
    #pragma unroll
    for (int it = 0; it < 16; it++) {
        int cid = tid + it*256;
        int row = cid >> 5, part = cid & 31;
        cpa16(&Bs[row][part*4], g_wout + (size_t)row*DP + part*4);
    }
    loadA(0, 0); CPA_COMMIT;

    float acc[2][8][4];
    #pragma unroll
    for (int mt = 0; mt < 2; mt++)
        #pragma unroll
        for (int nt = 0; nt < 8; nt++)
            #pragma unroll
            for (int r = 0; r < 4; r++) acc[mt][nt][r] = 0.f;

    for (int kt = 0; kt < 4; kt++) {
        CPA_WAIT0; __syncthreads();
        if (kt < 3) { loadA((kt+1)&1, (kt+1)*32); CPA_COMMIT; }
        int st = kt & 1;
        #pragma unroll
        for (int ks = 0; ks < 4; ks++) {
            int kk = ks*8;
            float a[2][4], b[8][2];
            #pragma unroll
            for (int mt = 0; mt < 2; mt++) {
                int mr = wm*32 + mt*16 + lrow;
                a[mt][0] = As[st][mr  ][kk+lq];
                a[mt][1] = As[st][mr+8][kk+lq];
                a[mt][2] = As[st][mr  ][kk+lq+4];
                a[mt][3] = As[st][mr+8][kk+lq+4];
            }
            #pragma unroll
            for (int nt = 0; nt < 8; nt++) {
                int nb = wn*64 + nt*8 + lrow;
                b[nt][0] = Bs[kt*32+kk+lq  ][nb];
                b[nt][1] = Bs[kt*32+kk+lq+4][nb];
            }
            #pragma unroll
            for (int mt = 0; mt < 2; mt++)
                #pragma unroll
                for (int nt = 0; nt < 8; nt++)
                    mma8(acc[mt][nt], a[mt], b[nt]);
        }
    }
    #pragma unroll
    for (int mt = 0; mt < 2; mt++)
        #pragma unroll
        for (int hf = 0; hf < 2; hf++) {
            int i = ib + wm*32 + mt*16 + lrow + hf*8;
            size_t row = (size_t)i*L + n;
            #pragma unroll
            for (int nt = 0; nt < 8; nt++) {
                int c = wn*64 + nt*8 + 2*lq;
                *(float2*)(out + row*DP + c) =
                    make_float2(acc[mt][nt][hf*2]   + bout[c],
                                acc[mt][nt][hf*2+1] + bout[c+1]);
            }
        }
}

// ---------------- launch ----------------
extern "C" void kernel_launch(void* const* d_in, const int* in_sizes, int n_in,
                              void* d_out, int out_size)
{
    const float* pair    = (const float*)d_in[0];
    const float* bias    = (const float*)d_in[1];
    const float* gamma_p = (const float*)d_in[2];
    const float* beta_p  = (const float*)d_in[3];
    const float* gamma_b = (const float*)d_in[4];
    const float* beta_b  = (const float*)d_in[5];
    const float* Wq      = (const float*)d_in[6];
    const float* Wk      = (const float*)d_in[7];
    const float* Wv      = (const float*)d_in[8];
    const float* Wb      = (const float*)d_in[9];
    const float* Wg      = (const float*)d_in[10];
    const float* bg      = (const float*)d_in[11];
    const float* Wout    = (const float*)d_in[12];
    const float* bout    = (const float*)d_in[13];
    float* out = (float*)d_out;

    const int smProj = (128*APAD + 2*128*WPAD) * 4;      // 206848 B
    const int smO    = (2*128*PADA + 2*32*PADB) * 4;     // 71680 B
    const int smOut  = (2*128*PADA + 128*PADB) * 4;      // 106496 B
    static int inited = 0;
    if (!inited) {
        cudaFuncSetAttribute(k_projf, cudaFuncAttributeMaxDynamicSharedMemorySize, smProj);
        cudaFuncSetAttribute(k_o,     cudaFuncAttributeMaxDynamicSharedMemorySize, smO);
        cudaFuncSetAttribute(k_out,   cudaFuncAttributeMaxDynamicSharedMemorySize, smOut);
        inited = 1;
    }

    k_prep    <<<320, 256>>>(Wq, Wk, Wv, Wg, Wout);
    k_bias    <<<LL/8, 256>>>(bias, gamma_b, beta_b, Wb);
    k_projf   <<<LL/128, 256, smProj>>>(pair, gamma_p, beta_p, bg);
    k_qk      <<<dim3(3, 3, NH*SPLIT), 256>>>();
    k_softmax <<<dim3(L, NH), 128>>>();
    k_o       <<<dim3(3, (L*DH)/128, NH), 256, smO>>>();
    k_out     <<<LL/128, 256, smOut>>>(bout, out);
}

// round 5
// speedup vs baseline: 3.5849x; 1.0476x over previous
#include <cuda_runtime.h>
#include <cuda_bf16.h>
#include <math.h>

#define L    384
#define DP   128
#define NH   4
#define DH   32
#define LL   (L*L)            // 147456
#define SPLIT 8
#define NSPL  (L/SPLIT)       // 48

// ---------------- scratch ----------------
__device__ __nv_bfloat16 g_qb[NH*LL*DH];     // q bf16: ((h*L+n)*L+i)*32+d
__device__ __nv_bfloat16 g_kb[NH*LL*DH];     // k bf16: ((h*L+n)*L+j)*32+d
__device__ float g_vT  [NH*LL*DH];           // v tf32-rounded: ((h*L+j)*L+n)*32+d
__device__ float g_gate[LL*DP];
__device__ float g_o   [LL*DP];              // gated + tf32-rounded, row n*L+i
__device__ float g_attn[NH*LL];              // softmax probs, tf32-rounded
__device__ float g_battn[NH*LL];             // [h][i][j]
__device__ float g_qkp [SPLIT*NH*LL];        // qk partials [s][h][i][j]
__device__ float g_w4  [4*DP*DP];            // tf32-rounded Wq|Wk|Wv|Wg
__device__ float g_wout[DP*DP];              // tf32-rounded Wout

// ---------------- helpers ----------------
__device__ __forceinline__ float tf32r(float x) {
    float y; asm("cvt.rna.tf32.f32 %0, %1;" : "=f"(y) : "f"(x)); return y;
}
__device__ __forceinline__ void cpa16(void* dst, const void* src) {
    unsigned d = (unsigned)__cvta_generic_to_shared(dst);
    asm volatile("cp.async.cg.shared.global [%0], [%1], 16;\n" :: "r"(d), "l"(src));
}
#define CPA_COMMIT asm volatile("cp.async.commit_group;\n" ::: "memory")
#define CPA_WAIT0  asm volatile("cp.async.wait_group 0;\n" ::: "memory")

__device__ __forceinline__ void mma8(float c[4], const float a[4], const float b[2]) {
    asm volatile(
        "mma.sync.aligned.m16n8k8.row.col.f32.tf32.tf32.f32 "
        "{%0,%1,%2,%3},{%4,%5,%6,%7},{%8,%9},{%0,%1,%2,%3};\n"
        : "+f"(c[0]), "+f"(c[1]), "+f"(c[2]), "+f"(c[3])
        : "r"(__float_as_uint(a[0])), "r"(__float_as_uint(a[1])),
          "r"(__float_as_uint(a[2])), "r"(__float_as_uint(a[3])),
          "r"(__float_as_uint(b[0])), "r"(__float_as_uint(b[1])));
}
__device__ __forceinline__ void mma16(float c[4], const unsigned a[4], const unsigned b[2]) {
    asm volatile(
        "mma.sync.aligned.m16n8k16.row.col.f32.bf16.bf16.f32 "
        "{%0,%1,%2,%3},{%4,%5,%6,%7},{%8,%9},{%0,%1,%2,%3};\n"
        : "+f"(c[0]), "+f"(c[1]), "+f"(c[2]), "+f"(c[3])
        : "r"(a[0]), "r"(a[1]), "r"(a[2]), "r"(a[3]), "r"(b[0]), "r"(b[1]));
}

// ---------------- kernel 0: pre-round weights ----------------
__global__ __launch_bounds__(256) void k_prep(const float* __restrict__ Wq,
                                              const float* __restrict__ Wk,
                                              const float* __restrict__ Wv,
                                              const float* __restrict__ Wg,
                                              const float* __restrict__ Wout)
{
    int id = blockIdx.x * 256 + threadIdx.x;
    if (id < 4*DP*DP) {
        int which = id >> 14, rem = id & (DP*DP - 1);
        const float* W = (which==0) ? Wq : (which==1) ? Wk : (which==2) ? Wv : Wg;
        g_w4[id] = tf32r(W[rem]);
    } else {
        int rem = id - 4*DP*DP;
        g_wout[rem] = tf32r(Wout[rem]);
    }
}

// ---------------- kernel 2: bias path (coalesced reads) ----------------
__global__ __launch_bounds__(256) void k_bias(const float* __restrict__ bias,
                                              const float* __restrict__ gamma,
                                              const float* __restrict__ beta,
                                              const float* __restrict__ Wb)
{
    int warp = (blockIdx.x * blockDim.x + threadIdx.x) >> 5;
    int lane = threadIdx.x & 31;
    if (warp >= LL) return;
    int j = warp / L, i = warp % L;       // consecutive warps -> consecutive rows j*L+i
    float4 x = ((const float4*)(bias + (size_t)warp * DP))[lane];   // row (j,i) of raw bias
    float s  = x.x + x.y + x.z + x.w;
    float ss = x.x*x.x + x.y*x.y + x.z*x.z + x.w*x.w;
    #pragma unroll
    for (int o = 16; o; o >>= 1) {
        s  += __shfl_xor_sync(0xffffffffu, s,  o);
        ss += __shfl_xor_sync(0xffffffffu, ss, o);
    }
    float mean = s * (1.0f/DP);
    float var  = ss * (1.0f/DP) - mean*mean;
    float inv  = rsqrtf(var + 1e-5f);
    float4 g = ((const float4*)gamma)[lane];
    float4 b = ((const float4*)beta )[lane];
    float y[4];
    y[0] = (x.x - mean)*inv*g.x + b.x;
    y[1] = (x.y - mean)*inv*g.y + b.y;
    y[2] = (x.z - mean)*inv*g.z + b.z;
    y[3] = (x.w - mean)*inv*g.w + b.w;
    float acc[NH] = {0.f, 0.f, 0.f, 0.f};
    #pragma unroll
    for (int t = 0; t < 4; t++) {
        int c = lane*4 + t;
        #pragma unroll
        for (int h = 0; h < NH; h++)
            acc[h] += y[t] * Wb[c*NH + h];
    }
    #pragma unroll
    for (int h = 0; h < NH; h++)
        #pragma unroll
        for (int o = 16; o; o >>= 1)
            acc[h] += __shfl_xor_sync(0xffffffffu, acc[h], o);
    // bias_t[i][j] = LN(bias[j][i]) @ Wb   -> store [h][i][j]
    if (lane == 0) {
        #pragma unroll
        for (int h = 0; h < NH; h++)
            g_battn[(size_t)h*LL + (size_t)i*L + j] = acc[h];
    }
}

// ---------------- kernel 3: fused LN + 4 projections, 512 threads ----------------
#define APAD 132
#define WPAD 136
__global__ __launch_bounds__(512) void k_projf(const float* __restrict__ pair,
                                               const float* __restrict__ gamma,
                                               const float* __restrict__ beta,
                                               const float* __restrict__ bg)
{
    extern __shared__ float sm[];
    float (*As)[APAD]      = (float(*)[APAD])sm;                    // [128][APAD]
    float (*Bs)[128][WPAD] = (float(*)[128][WPAD])(sm + 128*APAD);  // [2][128][WPAD]
    int m0 = blockIdx.x * 128;
    int n  = m0 / L;
    int i0 = m0 % L;
    int tid = threadIdx.x;
    int w = tid >> 5, lane = tid & 31;
    int wm = w >> 2, wn = w & 3;          // 4x4 warp grid, 32x32 warp tiles
    int lrow = lane >> 2, lq = lane & 3;

    #pragma unroll
    for (int it = 0; it < 8; it++) {
        int cid = tid + it*512;                 // 4096 16B chunks
        int row = cid >> 5, part = cid & 31;
        cpa16(&As[row][part*4], pair + ((size_t)(i0+row)*L + n)*DP + part*4);
    }
    CPA_COMMIT;
    #pragma unroll
    for (int it = 0; it < 8; it++) {
        int cid = tid + it*512;
        int row = cid >> 5, part = cid & 31;
        cpa16(&Bs[0][row][part*4], g_w4 + (size_t)row*DP + part*4);
    }
    CPA_COMMIT;
    CPA_WAIT0; __syncthreads();

    // LN in smem: warp w handles rows w*8 .. w*8+7
    {
        float4 gm = ((const float4*)gamma)[lane];
        float4 bt = ((const float4*)beta )[lane];
        #pragma unroll
        for (int r = 0; r < 8; r++) {
            int row = w*8 + r;
            float4 x = *(float4*)&As[row][lane*4];
            float s  = x.x + x.y + x.z + x.w;
            float ss = x.x*x.x + x.y*x.y + x.z*x.z + x.w*x.w;
            #pragma unroll
            for (int o = 16; o; o >>= 1) {
                s  += __shfl_xor_sync(0xffffffffu, s,  o);
                ss += __shfl_xor_sync(0xffffffffu, ss, o);
            }
            float mean = s * (1.0f/DP);
            float var  = ss * (1.0f/DP) - mean*mean;
            float inv  = rsqrtf(var + 1e-5f);
            float4 y;
            y.x = tf32r((x.x - mean)*inv*gm.x + bt.x);
            y.y = tf32r((x.y - mean)*inv*gm.y + bt.y);
            y.z = tf32r((x.z - mean)*inv*gm.z + bt.z);
            y.w = tf32r((x.w - mean)*inv*gm.w + bt.w);
            *(float4*)&As[row][lane*4] = y;
        }
    }
    __syncthreads();

    const float qscale = 0.17677669529663689f;
    const float kscale = 1.0f / (float)L;

    for (int which = 0; which < 4; which++) {
        int buf = which & 1;
        if (which < 3) {
            #pragma unroll
            for (int it = 0; it < 8; it++) {
                int cid = tid + it*512;
                int row = cid >> 5, part = cid & 31;
                cpa16(&Bs[buf^1][row][part*4],
                      g_w4 + (size_t)(which+1)*DP*DP + (size_t)row*DP + part*4);
            }
            CPA_COMMIT;
        }

        float acc[2][4][4];
        #pragma unroll
        for (int mt = 0; mt < 2; mt++)
            #pragma unroll
            for (int nt = 0; nt < 4; nt++)
                #pragma unroll
                for (int r = 0; r < 4; r++) acc[mt][nt][r] = 0.f;

        #pragma unroll 4
        for (int ks = 0; ks < 16; ks++) {
            int kk = ks*8;
            float a[2][4], b[4][2];
            #pragma unroll
            for (int mt = 0; mt < 2; mt++) {
                int mr = wm*32 + mt*16 + lrow;
                a[mt][0] = As[mr  ][kk+lq];
                a[mt][1] = As[mr+8][kk+lq];
                a[mt][2] = As[mr  ][kk+lq+4];
                a[mt][3] = As[mr+8][kk+lq+4];
            }
            #pragma unroll
            for (int nt = 0; nt < 4; nt++) {
                int nb = wn*32 + nt*8 + lrow;
                b[nt][0] = Bs[buf][kk+lq  ][nb];
                b[nt][1] = Bs[buf][kk+lq+4][nb];
            }
            #pragma unroll
            for (int mt = 0; mt < 2; mt++)
                #pragma unroll
                for (int nt = 0; nt < 4; nt++)
                    mma8(acc[mt][nt], a[mt], b[nt]);
        }

        #pragma unroll
        for (int mt = 0; mt < 2; mt++) {
            #pragma unroll
            for (int hf = 0; hf < 2; hf++) {
                int i = i0 + wm*32 + mt*16 + lrow + hf*8;
                #pragma unroll
                for (int nt = 0; nt < 4; nt++) {
                    int c = wn*32 + nt*8 + 2*lq;
                    float v0 = acc[mt][nt][hf*2+0];
                    float v1 = acc[mt][nt][hf*2+1];
                    if (which == 0) {
                        int h = c >> 5, d = c & 31;
                        __nv_bfloat162 qv;
                        qv.x = __float2bfloat16(v0*qscale);
                        qv.y = __float2bfloat16(v1*qscale);
                        *(__nv_bfloat162*)(g_qb + ((size_t)(h*L+n)*L + i)*DH + d) = qv;
                    } else if (which == 1) {
                        int h = c >> 5, d = c & 31;
                        __nv_bfloat162 kv;
                        kv.x = __float2bfloat16(v0*kscale);
                        kv.y = __float2bfloat16(v1*kscale);
                        *(__nv_bfloat162*)(g_kb + ((size_t)(h*L+n)*L + i)*DH + d) = kv;
                    } else if (which == 2) {
                        int h = c >> 5, d = c & 31;
                        *(float2*)(g_vT + ((size_t)(h*L+i)*L + n)*DH + d) =
                            make_float2(tf32r(v0), tf32r(v1));
                    } else {
                        v0 = 1.0f/(1.0f + expf(-(v0 + bg[c  ])));
                        v1 = 1.0f/(1.0f + expf(-(v1 + bg[c+1])));
                        *(float2*)(g_gate + ((size_t)(n*L+i))*DP + c) = make_float2(v0, v1);
                    }
                }
            }
        }
        if (which < 3) { CPA_WAIT0; __syncthreads(); }
    }
}

// ---------------- kernel 4: QK logits, bf16 MMA, SPLIT=8, 2 n per stage ----------------
__global__ __launch_bounds__(256) void k_qk()
{
    extern __shared__ __nv_bfloat16 smb[];
    __nv_bfloat16 (*Qs)[2][128][40] = (__nv_bfloat16(*)[2][128][40])smb;
    __nv_bfloat16 (*Ks)[2][128][40] = (__nv_bfloat16(*)[2][128][40])(smb + 2*2*128*40);
    int i0 = blockIdx.x * 128, j0 = blockIdx.y * 128;
    int h = blockIdx.z & 3, s = blockIdx.z >> 2;
    int tid = threadIdx.x;
    int w = tid >> 5, lane = tid & 31;
    int wm = w >> 1, wn = w & 1;
    int lrow = lane >> 2, lq = lane & 3;
    const __nv_bfloat16* Qg = g_qb + (size_t)h*L*L*DH;
    const __nv_bfloat16* Kg = g_kb + (size_t)h*L*L*DH;

    auto load = [&](int st, int n) {   // loads n and n+1
        #pragma unroll
        for (int it = 0; it < 4; it++) {
            int cid = tid + it*256;            // 1024 chunks: 2n x 128row x 4part
            int n2 = cid >> 9, rem = cid & 511;
            int row = rem >> 2, part = rem & 3;
            cpa16(&Qs[st][n2][row][part*8], Qg + ((size_t)(n+n2)*L + i0 + row)*DH + part*8);
        }
        #pragma unroll
        for (int it = 0; it < 4; it++) {
            int cid = tid + it*256;
            int n2 = cid >> 9, rem = cid & 511;
            int row = rem >> 2, part = rem & 3;
            cpa16(&Ks[st][n2][row][part*8], Kg + ((size_t)(n+n2)*L + j0 + row)*DH + part*8);
        }
    };

    float acc[2][8][4];
    #pragma unroll
    for (int mt = 0; mt < 2; mt++)
        #pragma unroll
        for (int nt = 0; nt < 8; nt++)
            #pragma unroll
            for (int r = 0; r < 4; r++) acc[mt][nt][r] = 0.f;

    load(0, s*NSPL); CPA_COMMIT;
    const int IT = NSPL/2;   // 24
    for (int it = 0; it < IT; it++) {
        CPA_WAIT0; __syncthreads();
        if (it+1 < IT) { load((it+1)&1, s*NSPL + (it+1)*2); CPA_COMMIT; }
        int st = it & 1;
        #pragma unroll
        for (int n2 = 0; n2 < 2; n2++) {
            #pragma unroll
            for (int ks = 0; ks < 2; ks++) {
                int cb = ks*16;
                unsigned a[2][4], b[8][2];
                #pragma unroll
                for (int mt = 0; mt < 2; mt++) {
                    int mr = wm*32 + mt*16 + lrow;
                    a[mt][0] = *(const unsigned*)&Qs[st][n2][mr  ][cb+2*lq];
                    a[mt][1] = *(const unsigned*)&Qs[st][n2][mr+8][cb+2*lq];
                    a[mt][2] = *(const unsigned*)&Qs[st][n2][mr  ][cb+2*lq+8];
                    a[mt][3] = *(const unsigned*)&Qs[st][n2][mr+8][cb+2*lq+8];
                }
                #pragma unroll
                for (int nt = 0; nt < 8; nt++) {
                    int nb = wn*64 + nt*8 + lrow;
                    b[nt][0] = *(const unsigned*)&Ks[st][n2][nb][cb+2*lq];
                    b[nt][1] = *(const unsigned*)&Ks[st][n2][nb][cb+2*lq+8];
                }
                #pragma unroll
                for (int mt = 0; mt < 2; mt++)
                    #pragma unroll
                    for (int nt = 0; nt < 8; nt++)
                        mma16(acc[mt][nt], a[mt], b[nt]);
            }
        }
        __syncthreads();
    }
    float* dst = g_qkp + (size_t)(s*NH + h)*LL;
    #pragma unroll
    for (int mt = 0; mt < 2; mt++)
        #pragma unroll
        for (int hf = 0; hf < 2; hf++) {
            int i = i0 + wm*32 + mt*16 + lrow + hf*8;
            #pragma unroll
            for (int nt = 0; nt < 8; nt++) {
                int j = j0 + wn*64 + nt*8 + 2*lq;
                *(float2*)(dst + (size_t)i*L + j) =
                    make_float2(acc[mt][nt][hf*2], acc[mt][nt][hf*2+1]);
            }
        }
}

// ---------------- kernel 5: softmax ----------------
__global__ __launch_bounds__(128) void k_softmax()
{
    __shared__ float redm[4], reds[4];
    int i = blockIdx.x, h = blockIdx.y;
    int tid = threadIdx.x;
    float v[3];
    float mx = -1e30f;
    #pragma unroll
    for (int r = 0; r < 3; r++) {
        int j = tid + r*128;
        float a = g_battn[(size_t)h*LL + (size_t)i*L + j];
        #pragma unroll
        for (int s = 0; s < SPLIT; s++)
            a += g_qkp[(size_t)(s*NH + h)*LL + (size_t)i*L + j];
        v[r] = a;
        mx = fmaxf(mx, a);
    }
    #pragma unroll
    for (int o = 16; o; o >>= 1) mx = fmaxf(mx, __shfl_xor_sync(0xffffffffu, mx, o));
    if ((tid & 31) == 0) redm[tid >> 5] = mx;
    __syncthreads();
    mx = fmaxf(fmaxf(redm[0], redm[1]), fmaxf(redm[2], redm[3]));
    float se = 0.f;
    #pragma unroll
    for (int r = 0; r < 3; r++) { v[r] = expf(v[r] - mx); se += v[r]; }
    #pragma unroll
    for (int o = 16; o; o >>= 1) se += __shfl_xor_sync(0xffffffffu, se, o);
    if ((tid & 31) == 0) reds[tid >> 5] = se;
    __syncthreads();
    se = reds[0] + reds[1] + reds[2] + reds[3];
    float inv = 1.0f / se;
    float* dst = g_attn + (size_t)h*LL + (size_t)i*L;
    #pragma unroll
    for (int r = 0; r < 3; r++) dst[tid + r*128] = tf32r(v[r] * inv);
}

// ---------------- kernel 6: AV per-head GEMM + gate epilogue, 512 threads ----------------
#define PADA 36
#define PADB 136
__global__ __launch_bounds__(512) void k_o()
{
    extern __shared__ float sm[];
    float (*As)[128][PADA] = (float(*)[128][PADA])sm;
    float (*Bs)[32][PADB]  = (float(*)[32][PADB])(sm + 2*128*PADA);
    int i0  = blockIdx.x * 128;
    int nd0 = blockIdx.y * 128;
    int h   = blockIdx.z;
    int tid = threadIdx.x;
    int w = tid >> 5, lane = tid & 31;
    int wm = w >> 2, wn = w & 3;
    int lrow = lane >> 2, lq = lane & 3;
    const float* A = g_attn + (size_t)h*LL;
    const float* B = g_vT + (size_t)h*L*L*DH;

    auto load = [&](int st, int k0) {
        #pragma unroll
        for (int it = 0; it < 2; it++) {
            int cid = tid + it*512;
            int row = cid >> 3, part = cid & 7;
            cpa16(&As[st][row][part*4], A + (size_t)(i0+row)*L + k0 + part*4);
        }
        #pragma unroll
        for (int it = 0; it < 2; it++) {
            int cid = tid + it*512;
            int row = cid >> 5, part = cid & 31;
            cpa16(&Bs[st][row][part*4], B + (size_t)(k0+row)*(L*DH) + nd0 + part*4);
        }
    };

    float acc[2][4][4];
    #pragma unroll
    for (int mt = 0; mt < 2; mt++)
        #pragma unroll
        for (int nt = 0; nt < 4; nt++)
            #pragma unroll
            for (int r = 0; r < 4; r++) acc[mt][nt][r] = 0.f;

    load(0, 0); CPA_COMMIT;
    for (int kt = 0; kt < 12; kt++) {
        CPA_WAIT0; __syncthreads();
        if (kt < 11) { load((kt+1)&1, (kt+1)*32); CPA_COMMIT; }
        int st = kt & 1;
        #pragma unroll
        for (int ks = 0; ks < 4; ks++) {
            int kk = ks*8;
            float a[2][4], b[4][2];
            #pragma unroll
            for (int mt = 0; mt < 2; mt++) {
                int mr = wm*32 + mt*16 + lrow;
                a[mt][0] = As[st][mr  ][kk+lq];
                a[mt][1] = As[st][mr+8][kk+lq];
                a[mt][2] = As[st][mr  ][kk+lq+4];
                a[mt][3] = As[st][mr+8][kk+lq+4];
            }
            #pragma unroll
            for (int nt = 0; nt < 4; nt++) {
                int nb = wn*32 + nt*8 + lrow;
                b[nt][0] = Bs[st][kk+lq  ][nb];
                b[nt][1] = Bs[st][kk+lq+4][nb];
            }
            #pragma unroll
            for (int mt = 0; mt < 2; mt++)
                #pragma unroll
                for (int nt = 0; nt < 4; nt++)
                    mma8(acc[mt][nt], a[mt], b[nt]);
        }
        __syncthreads();
    }
    #pragma unroll
    for (int mt = 0; mt < 2; mt++)
        #pragma unroll
        for (int hf = 0; hf < 2; hf++) {
            int i = i0 + wm*32 + mt*16 + lrow + hf*8;
            #pragma unroll
            for (int nt = 0; nt < 4; nt++) {
                int nd = nd0 + wn*32 + nt*8 + 2*lq;
                int n = nd >> 5, d = nd & 31;
                size_t off = (size_t)(n*L + i)*DP + h*DH + d;
                float2 gv = *(const float2*)(g_gate + off);
                *(float2*)(g_o + off) =
                    make_float2(tf32r(acc[mt][nt][hf*2]  * gv.x),
                                tf32r(acc[mt][nt][hf*2+1]* gv.y));
            }
        }
}

// ---------------- kernel 7: out = g_o @ Wout + bout, 512 threads ----------------
__global__ __launch_bounds__(512) void k_out(const float* __restrict__ bout,
                                             float* __restrict__ out)
{
    extern __shared__ float sm[];
    float (*As)[128][PADA] = (float(*)[128][PADA])sm;
    float (*Bs)[PADB]      = (float(*)[PADB])(sm + 2*128*PADA);
    int m0 = blockIdx.x * 128;
    int n  = m0 / L;
    int ib = m0 % L;
    int tid = threadIdx.x;
    int w = tid >> 5, lane = tid & 31;
    int wm = w >> 2, wn = w & 3;
    int lrow = lane >> 2, lq = lane & 3;

    auto loadA = [&](int st, int k0) {
        #pragma unroll
        for (int it = 0; it < 2; it++) {
            int cid = tid + it*512;
            int row = cid >> 3, part = cid & 7;
            cpa16(&As[st][row][part*4], g_o + (size_t)(m0+row)*DP + k0 + part*4);
        }
    };
    #pragma unroll
    for (int it = 0; it < 8; it++) {
        int cid = tid + it*512;
        int row = cid >> 5, part = cid & 31;
        cpa16(&Bs[row][part*4], g_wout + (size_t)row*DP + part*4);
    }
    loadA(0, 0); CPA_COMMIT;

    float acc[2][4][4];
    #pragma unroll
    for (int mt = 0; mt < 2; mt++)
        #pragma unroll
        for (int nt = 0; nt < 4; nt++)
            #pragma unroll
            for (int r = 0; r < 4; r++) acc[mt][nt][r] = 0.f;

    for (int kt = 0; kt < 4; kt++) {
        CPA_WAIT0; __syncthreads();
        if (kt < 3) { loadA((kt+1)&1, (kt+1)*32); CPA_COMMIT; }
        int st = kt & 1;
        #pragma unroll
        for (int ks = 0; ks < 4; ks++) {
            int kk = ks*8;
            float a[2][4], b[4][2];
            #pragma unroll
            for (int mt = 0; mt < 2; mt++) {
                int mr = wm*32 + mt*16 + lrow;
                a[mt][0] = As[st][mr  ][kk+lq];
                a[mt][1] = As[st][mr+8][kk+lq];
                a[mt][2] = As[st][mr  ][kk+lq+4];
                a[mt][3] = As[st][mr+8][kk+lq+4];
            }
            #pragma unroll
            for (int nt = 0; nt < 4; nt++) {
                int nb = wn*32 + nt*8 + lrow;
                b[nt][0] = Bs[kt*32+kk+lq  ][nb];
                b[nt][1] = Bs[kt*32+kk+lq+4][nb];
            }
            #pragma unroll
            for (int mt = 0; mt < 2; mt++)
                #pragma unroll
                for (int nt = 0; nt < 4; nt++)
                    mma8(acc[mt][nt], a[mt], b[nt]);
        }
        __syncthreads();
    }
    #pragma unroll
    for (int mt = 0; mt < 2; mt++)
        #pragma unroll
        for (int hf = 0; hf < 2; hf++) {
            int i = ib + wm*32 + mt*16 + lrow + hf*8;
            size_t row = (size_t)i*L + n;
            #pragma unroll
            for (int nt = 0; nt < 4; nt++) {
                int c = wn*32 + nt*8 + 2*lq;
                *(float2*)(out + row*DP + c) =
                    make_float2(acc[mt][nt][hf*2]   + bout[c],
                                acc[mt][nt][hf*2+1] + bout[c+1]);
            }
        }
}

// ---------------- launch ----------------
extern "C" void kernel_launch(void* const* d_in, const int* in_sizes, int n_in,
                              void* d_out, int out_size)
{
    const float* pair    = (const float*)d_in[0];
    const float* bias    = (const float*)d_in[1];
    const float* gamma_p = (const float*)d_in[2];
    const float* beta_p  = (const float*)d_in[3];
    const float* gamma_b = (const float*)d_in[4];
    const float* beta_b  = (const float*)d_in[5];
    const float* Wq      = (const float*)d_in[6];
    const float* Wk      = (const float*)d_in[7];
    const float* Wv      = (const float*)d_in[8];
    const float* Wb      = (const float*)d_in[9];
    const float* Wg      = (const float*)d_in[10];
    const float* bg      = (const float*)d_in[11];
    const float* Wout    = (const float*)d_in[12];
    const float* bout    = (const float*)d_in[13];
    float* out = (float*)d_out;

    const int smProj = (128*APAD + 2*128*WPAD) * 4;      // 206848 B
    const int smQK   = 2 * (2*2*128*40) * 2;             // 81920 B
    const int smO    = (2*128*PADA + 2*32*PADB) * 4;     // 71680 B
    const int smOut  = (2*128*PADA + 128*PADB) * 4;      // 106496 B
    static int inited = 0;
    if (!inited) {
        cudaFuncSetAttribute(k_projf, cudaFuncAttributeMaxDynamicSharedMemorySize, smProj);
        cudaFuncSetAttribute(k_qk,    cudaFuncAttributeMaxDynamicSharedMemorySize, smQK);
        cudaFuncSetAttribute(k_o,     cudaFuncAttributeMaxDynamicSharedMemorySize, smO);
        cudaFuncSetAttribute(k_out,   cudaFuncAttributeMaxDynamicSharedMemorySize, smOut);
        inited = 1;
    }

    k_prep    <<<320, 256>>>(Wq, Wk, Wv, Wg, Wout);
    k_bias    <<<LL/8, 256>>>(bias, gamma_b, beta_b, Wb);
    k_projf   <<<LL/128, 512, smProj>>>(pair, gamma_p, beta_p, bg);
    k_qk      <<<dim3(3, 3, NH*SPLIT), 256, smQK>>>();
    k_softmax <<<dim3(L, NH), 128>>>();
    k_o       <<<dim3(3, (L*DH)/128, NH), 512, smO>>>();
    k_out     <<<LL/128, 512, smOut>>>(bout, out);
}

// round 6
// speedup vs baseline: 3.6229x; 1.0106x over previous
#include <cuda_runtime.h>
#include <cuda_bf16.h>
#include <math.h>

#define L    384
#define DP   128
#define NH   4
#define DH   32
#define LL   (L*L)            // 147456
#define SPLIT 8
#define NSPL  (L/SPLIT)       // 48

// ---------------- scratch ----------------
__device__ __nv_bfloat16 g_qb[NH*LL*DH];     // q bf16: ((h*L+n)*L+i)*32+d
__device__ __nv_bfloat16 g_kb[NH*LL*DH];     // k bf16: ((h*L+n)*L+j)*32+d
__device__ float g_vT  [NH*LL*DH];           // v tf32-rounded: ((h*L+j)*L+n)*32+d
__device__ float g_gate[LL*DP];
__device__ float g_o   [LL*DP];              // gated + tf32-rounded, row n*L+i
__device__ float g_attn[NH*LL];              // softmax probs, tf32-rounded
__device__ float g_battn[NH*LL];             // [h][i][j]
__device__ float g_qkp [SPLIT*NH*LL];        // qk partials [s][h][i][j]
__device__ float g_w4  [4*DP*DP];            // tf32-rounded Wq|Wk|Wv|Wg
__device__ float g_wout[DP*DP];              // tf32-rounded Wout

// ---------------- helpers ----------------
__device__ __forceinline__ float tf32r(float x) {
    float y; asm("cvt.rna.tf32.f32 %0, %1;" : "=f"(y) : "f"(x)); return y;
}
__device__ __forceinline__ void cpa16(void* dst, const void* src) {
    unsigned d = (unsigned)__cvta_generic_to_shared(dst);
    asm volatile("cp.async.cg.shared.global [%0], [%1], 16;\n" :: "r"(d), "l"(src));
}
#define CPA_COMMIT asm volatile("cp.async.commit_group;\n" ::: "memory")
#define CPA_WAIT0  asm volatile("cp.async.wait_group 0;\n" ::: "memory")

__device__ __forceinline__ void mma8(float c[4], const float a[4], const float b[2]) {
    asm volatile(
        "mma.sync.aligned.m16n8k8.row.col.f32.tf32.tf32.f32 "
        "{%0,%1,%2,%3},{%4,%5,%6,%7},{%8,%9},{%0,%1,%2,%3};\n"
        : "+f"(c[0]), "+f"(c[1]), "+f"(c[2]), "+f"(c[3])
        : "r"(__float_as_uint(a[0])), "r"(__float_as_uint(a[1])),
          "r"(__float_as_uint(a[2])), "r"(__float_as_uint(a[3])),
          "r"(__float_as_uint(b[0])), "r"(__float_as_uint(b[1])));
}
__device__ __forceinline__ void mma16(float c[4], const unsigned a[4], const unsigned b[2]) {
    asm volatile(
        "mma.sync.aligned.m16n8k16.row.col.f32.bf16.bf16.f32 "
        "{%0,%1,%2,%3},{%4,%5,%6,%7},{%8,%9},{%0,%1,%2,%3};\n"
        : "+f"(c[0]), "+f"(c[1]), "+f"(c[2]), "+f"(c[3])
        : "r"(a[0]), "r"(a[1]), "r"(a[2]), "r"(a[3]), "r"(b[0]), "r"(b[1]));
}
#define LDSM4(r0,r1,r2,r3,addr) \
    asm volatile("ldmatrix.sync.aligned.m8n8.x4.shared.b16 {%0,%1,%2,%3}, [%4];" \
                 : "=r"(r0), "=r"(r1), "=r"(r2), "=r"(r3) : "r"(addr))

// ---------------- kernel 0: pre-round weights ----------------
__global__ __launch_bounds__(256) void k_prep(const float* __restrict__ Wq,
                                              const float* __restrict__ Wk,
                                              const float* __restrict__ Wv,
                                              const float* __restrict__ Wg,
                                              const float* __restrict__ Wout)
{
    int id = blockIdx.x * 256 + threadIdx.x;
    if (id < 4*DP*DP) {
        int which = id >> 14, rem = id & (DP*DP - 1);
        const float* W = (which==0) ? Wq : (which==1) ? Wk : (which==2) ? Wv : Wg;
        g_w4[id] = tf32r(W[rem]);
    } else {
        int rem = id - 4*DP*DP;
        g_wout[rem] = tf32r(Wout[rem]);
    }
}

// ---------------- kernel 2: bias path (coalesced reads) ----------------
__global__ __launch_bounds__(256) void k_bias(const float* __restrict__ bias,
                                              const float* __restrict__ gamma,
                                              const float* __restrict__ beta,
                                              const float* __restrict__ Wb)
{
    int warp = (blockIdx.x * blockDim.x + threadIdx.x) >> 5;
    int lane = threadIdx.x & 31;
    if (warp >= LL) return;
    int j = warp / L, i = warp % L;
    float4 x = ((const float4*)(bias + (size_t)warp * DP))[lane];
    float s  = x.x + x.y + x.z + x.w;
    float ss = x.x*x.x + x.y*x.y + x.z*x.z + x.w*x.w;
    #pragma unroll
    for (int o = 16; o; o >>= 1) {
        s  += __shfl_xor_sync(0xffffffffu, s,  o);
        ss += __shfl_xor_sync(0xffffffffu, ss, o);
    }
    float mean = s * (1.0f/DP);
    float var  = ss * (1.0f/DP) - mean*mean;
    float inv  = rsqrtf(var + 1e-5f);
    float4 g = ((const float4*)gamma)[lane];
    float4 b = ((const float4*)beta )[lane];
    float y[4];
    y[0] = (x.x - mean)*inv*g.x + b.x;
    y[1] = (x.y - mean)*inv*g.y + b.y;
    y[2] = (x.z - mean)*inv*g.z + b.z;
    y[3] = (x.w - mean)*inv*g.w + b.w;
    float acc[NH] = {0.f, 0.f, 0.f, 0.f};
    #pragma unroll
    for (int t = 0; t < 4; t++) {
        int c = lane*4 + t;
        #pragma unroll
        for (int h = 0; h < NH; h++)
            acc[h] += y[t] * Wb[c*NH + h];
    }
    #pragma unroll
    for (int h = 0; h < NH; h++)
        #pragma unroll
        for (int o = 16; o; o >>= 1)
            acc[h] += __shfl_xor_sync(0xffffffffu, acc[h], o);
    if (lane == 0) {
        #pragma unroll
        for (int h = 0; h < NH; h++)
            g_battn[(size_t)h*LL + (size_t)i*L + j] = acc[h];
    }
}

// ---------------- kernel 3: fused LN + 4 projections, 512 threads ----------------
#define APAD 132
#define WPAD 136
__global__ __launch_bounds__(512) void k_projf(const float* __restrict__ pair,
                                               const float* __restrict__ gamma,
                                               const float* __restrict__ beta,
                                               const float* __restrict__ bg)
{
    extern __shared__ float sm[];
    float (*As)[APAD]      = (float(*)[APAD])sm;
    float (*Bs)[128][WPAD] = (float(*)[128][WPAD])(sm + 128*APAD);
    int m0 = blockIdx.x * 128;
    int n  = m0 / L;
    int i0 = m0 % L;
    int tid = threadIdx.x;
    int w = tid >> 5, lane = tid & 31;
    int wm = w >> 2, wn = w & 3;
    int lrow = lane >> 2, lq = lane & 3;

    #pragma unroll
    for (int it = 0; it < 8; it++) {
        int cid = tid + it*512;
        int row = cid >> 5, part = cid & 31;
        cpa16(&As[row][part*4], pair + ((size_t)(i0+row)*L + n)*DP + part*4);
    }
    CPA_COMMIT;
    #pragma unroll
    for (int it = 0; it < 8; it++) {
        int cid = tid + it*512;
        int row = cid >> 5, part = cid & 31;
        cpa16(&Bs[0][row][part*4], g_w4 + (size_t)row*DP + part*4);
    }
    CPA_COMMIT;
    CPA_WAIT0; __syncthreads();

    {
        float4 gm = ((const float4*)gamma)[lane];
        float4 bt = ((const float4*)beta )[lane];
        #pragma unroll
        for (int r = 0; r < 8; r++) {
            int row = w*8 + r;
            float4 x = *(float4*)&As[row][lane*4];
            float s  = x.x + x.y + x.z + x.w;
            float ss = x.x*x.x + x.y*x.y + x.z*x.z + x.w*x.w;
            #pragma unroll
            for (int o = 16; o; o >>= 1) {
                s  += __shfl_xor_sync(0xffffffffu, s,  o);
                ss += __shfl_xor_sync(0xffffffffu, ss, o);
            }
            float mean = s * (1.0f/DP);
            float var  = ss * (1.0f/DP) - mean*mean;
            float inv  = rsqrtf(var + 1e-5f);
            float4 y;
            y.x = tf32r((x.x - mean)*inv*gm.x + bt.x);
            y.y = tf32r((x.y - mean)*inv*gm.y + bt.y);
            y.z = tf32r((x.z - mean)*inv*gm.z + bt.z);
            y.w = tf32r((x.w - mean)*inv*gm.w + bt.w);
            *(float4*)&As[row][lane*4] = y;
        }
    }
    __syncthreads();

    const float qscale = 0.17677669529663689f;
    const float kscale = 1.0f / (float)L;

    for (int which = 0; which < 4; which++) {
        int buf = which & 1;
        if (which < 3) {
            #pragma unroll
            for (int it = 0; it < 8; it++) {
                int cid = tid + it*512;
                int row = cid >> 5, part = cid & 31;
                cpa16(&Bs[buf^1][row][part*4],
                      g_w4 + (size_t)(which+1)*DP*DP + (size_t)row*DP + part*4);
            }
            CPA_COMMIT;
        }

        float acc[2][4][4];
        #pragma unroll
        for (int mt = 0; mt < 2; mt++)
            #pragma unroll
            for (int nt = 0; nt < 4; nt++)
                #pragma unroll
                for (int r = 0; r < 4; r++) acc[mt][nt][r] = 0.f;

        #pragma unroll 4
        for (int ks = 0; ks < 16; ks++) {
            int kk = ks*8;
            float a[2][4], b[4][2];
            #pragma unroll
            for (int mt = 0; mt < 2; mt++) {
                int mr = wm*32 + mt*16 + lrow;
                a[mt][0] = As[mr  ][kk+lq];
                a[mt][1] = As[mr+8][kk+lq];
                a[mt][2] = As[mr  ][kk+lq+4];
                a[mt][3] = As[mr+8][kk+lq+4];
            }
            #pragma unroll
            for (int nt = 0; nt < 4; nt++) {
                int nb = wn*32 + nt*8 + lrow;
                b[nt][0] = Bs[buf][kk+lq  ][nb];
                b[nt][1] = Bs[buf][kk+lq+4][nb];
            }
            #pragma unroll
            for (int mt = 0; mt < 2; mt++)
                #pragma unroll
                for (int nt = 0; nt < 4; nt++)
                    mma8(acc[mt][nt], a[mt], b[nt]);
        }

        #pragma unroll
        for (int mt = 0; mt < 2; mt++) {
            #pragma unroll
            for (int hf = 0; hf < 2; hf++) {
                int i = i0 + wm*32 + mt*16 + lrow + hf*8;
                #pragma unroll
                for (int nt = 0; nt < 4; nt++) {
                    int c = wn*32 + nt*8 + 2*lq;
                    float v0 = acc[mt][nt][hf*2+0];
                    float v1 = acc[mt][nt][hf*2+1];
                    if (which == 0) {
                        int h = c >> 5, d = c & 31;
                        __nv_bfloat162 qv;
                        qv.x = __float2bfloat16(v0*qscale);
                        qv.y = __float2bfloat16(v1*qscale);
                        *(__nv_bfloat162*)(g_qb + ((size_t)(h*L+n)*L + i)*DH + d) = qv;
                    } else if (which == 1) {
                        int h = c >> 5, d = c & 31;
                        __nv_bfloat162 kv;
                        kv.x = __float2bfloat16(v0*kscale);
                        kv.y = __float2bfloat16(v1*kscale);
                        *(__nv_bfloat162*)(g_kb + ((size_t)(h*L+n)*L + i)*DH + d) = kv;
                    } else if (which == 2) {
                        int h = c >> 5, d = c & 31;
                        *(float2*)(g_vT + ((size_t)(h*L+i)*L + n)*DH + d) =
                            make_float2(tf32r(v0), tf32r(v1));
                    } else {
                        v0 = 1.0f/(1.0f + expf(-(v0 + bg[c  ])));
                        v1 = 1.0f/(1.0f + expf(-(v1 + bg[c+1])));
                        *(float2*)(g_gate + ((size_t)(n*L+i))*DP + c) = make_float2(v0, v1);
                    }
                }
            }
        }
        if (which < 3) { CPA_WAIT0; __syncthreads(); }
    }
}

// ---------------- kernel 4: QK logits, bf16 MMA + ldmatrix ----------------
__global__ __launch_bounds__(256, 2) void k_qk()
{
    extern __shared__ __nv_bfloat16 smb[];
    // Qs: [2 st][2 n2][128][40], Ks same, 80B row stride
    __nv_bfloat16* Qs = smb;
    __nv_bfloat16* Ks = smb + 2*2*128*40;
    int i0 = blockIdx.x * 128, j0 = blockIdx.y * 128;
    int h = blockIdx.z & 3, s = blockIdx.z >> 2;
    int tid = threadIdx.x;
    int w = tid >> 5, lane = tid & 31;
    int wm = w >> 1, wn = w & 1;
    int lrow = lane >> 2, lq = lane & 3;
    const __nv_bfloat16* Qg = g_qb + (size_t)h*L*L*DH;
    const __nv_bfloat16* Kg = g_kb + (size_t)h*L*L*DH;

    unsigned qBase = (unsigned)__cvta_generic_to_shared(Qs);
    unsigned kBase = (unsigned)__cvta_generic_to_shared(Ks);
    // lane-dependent offsets (bytes)
    unsigned aLane = (unsigned)((lane & 15)*80 + ((lane >> 4) & 1)*16);
    unsigned bLane = (unsigned)((((lane >> 4) & 1)*8 + (lane & 7))*80 + ((lane >> 3) & 1)*16);

    auto load = [&](int st, int n) {   // loads n and n+1
        #pragma unroll
        for (int it = 0; it < 4; it++) {
            int cid = tid + it*256;
            int n2 = cid >> 9, rem = cid & 511;
            int row = rem >> 2, part = rem & 3;
            cpa16(Qs + ((st*2 + n2)*128 + row)*40 + part*8,
                  Qg + ((size_t)(n+n2)*L + i0 + row)*DH + part*8);
        }
        #pragma unroll
        for (int it = 0; it < 4; it++) {
            int cid = tid + it*256;
            int n2 = cid >> 9, rem = cid & 511;
            int row = rem >> 2, part = rem & 3;
            cpa16(Ks + ((st*2 + n2)*128 + row)*40 + part*8,
                  Kg + ((size_t)(n+n2)*L + j0 + row)*DH + part*8);
        }
    };

    float acc[2][8][4];
    #pragma unroll
    for (int mt = 0; mt < 2; mt++)
        #pragma unroll
        for (int nt = 0; nt < 8; nt++)
            #pragma unroll
            for (int r = 0; r < 4; r++) acc[mt][nt][r] = 0.f;

    load(0, s*NSPL); CPA_COMMIT;
    const int IT = NSPL/2;   // 24
    for (int it = 0; it < IT; it++) {
        CPA_WAIT0; __syncthreads();
        if (it+1 < IT) { load((it+1)&1, s*NSPL + (it+1)*2); CPA_COMMIT; }
        int st = it & 1;
        #pragma unroll
        for (int n2 = 0; n2 < 2; n2++) {
            unsigned qTile = qBase + (unsigned)((st*2 + n2)*128*80);
            unsigned kTile = kBase + (unsigned)((st*2 + n2)*128*80);
            #pragma unroll
            for (int ks = 0; ks < 2; ks++) {
                unsigned a[2][4], b[8][2];
                #pragma unroll
                for (int mt = 0; mt < 2; mt++) {
                    unsigned addr = qTile + (unsigned)((wm*32 + mt*16)*80 + ks*32) + aLane;
                    LDSM4(a[mt][0], a[mt][1], a[mt][2], a[mt][3], addr);
                }
                #pragma unroll
                for (int np = 0; np < 4; np++) {   // nt pair: 2np, 2np+1
                    unsigned addr = kTile + (unsigned)((wn*64 + np*16)*80 + ks*32) + bLane;
                    LDSM4(b[2*np][0], b[2*np][1], b[2*np+1][0], b[2*np+1][1], addr);
                }
                #pragma unroll
                for (int mt = 0; mt < 2; mt++)
                    #pragma unroll
                    for (int nt = 0; nt < 8; nt++)
                        mma16(acc[mt][nt], a[mt], b[nt]);
            }
        }
    }
    float* dst = g_qkp + (size_t)(s*NH + h)*LL;
    #pragma unroll
    for (int mt = 0; mt < 2; mt++)
        #pragma unroll
        for (int hf = 0; hf < 2; hf++) {
            int i = i0 + wm*32 + mt*16 + lrow + hf*8;
            #pragma unroll
            for (int nt = 0; nt < 8; nt++) {
                int j = j0 + wn*64 + nt*8 + 2*lq;
                *(float2*)(dst + (size_t)i*L + j) =
                    make_float2(acc[mt][nt][hf*2], acc[mt][nt][hf*2+1]);
            }
        }
}

// ---------------- kernel 5: softmax ----------------
__global__ __launch_bounds__(128) void k_softmax()
{
    __shared__ float redm[4], reds[4];
    int i = blockIdx.x, h = blockIdx.y;
    int tid = threadIdx.x;
    float v[3];
    float mx = -1e30f;
    #pragma unroll
    for (int r = 0; r < 3; r++) {
        int j = tid + r*128;
        float a = g_battn[(size_t)h*LL + (size_t)i*L + j];
        #pragma unroll
        for (int s = 0; s < SPLIT; s++)
            a += g_qkp[(size_t)(s*NH + h)*LL + (size_t)i*L + j];
        v[r] = a;
        mx = fmaxf(mx, a);
    }
    #pragma unroll
    for (int o = 16; o; o >>= 1) mx = fmaxf(mx, __shfl_xor_sync(0xffffffffu, mx, o));
    if ((tid & 31) == 0) redm[tid >> 5] = mx;
    __syncthreads();
    mx = fmaxf(fmaxf(redm[0], redm[1]), fmaxf(redm[2], redm[3]));
    float se = 0.f;
    #pragma unroll
    for (int r = 0; r < 3; r++) { v[r] = expf(v[r] - mx); se += v[r]; }
    #pragma unroll
    for (int o = 16; o; o >>= 1) se += __shfl_xor_sync(0xffffffffu, se, o);
    if ((tid & 31) == 0) reds[tid >> 5] = se;
    __syncthreads();
    se = reds[0] + reds[1] + reds[2] + reds[3];
    float inv = 1.0f / se;
    float* dst = g_attn + (size_t)h*LL + (size_t)i*L;
    #pragma unroll
    for (int r = 0; r < 3; r++) dst[tid + r*128] = tf32r(v[r] * inv);
}

// ---------------- kernel 6: AV per-head GEMM + gate epilogue, 256 thr 2 CTA ----------------
#define PADA 36
#define PADB 136
__global__ __launch_bounds__(256, 2) void k_o()
{
    extern __shared__ float sm[];
    float (*As)[128][PADA] = (float(*)[128][PADA])sm;
    float (*Bs)[32][PADB]  = (float(*)[32][PADB])(sm + 2*128*PADA);
    int i0  = blockIdx.x * 128;
    int nd0 = blockIdx.y * 128;
    int h   = blockIdx.z;
    int tid = threadIdx.x;
    int w = tid >> 5, lane = tid & 31;
    int wm = w >> 1, wn = w & 1;
    int lrow = lane >> 2, lq = lane & 3;
    const float* A = g_attn + (size_t)h*LL;
    const float* B = g_vT + (size_t)h*L*L*DH;

    auto load = [&](int st, int k0) {
        #pragma unroll
        for (int it = 0; it < 4; it++) {
            int cid = tid + it*256;
            int row = cid >> 3, part = cid & 7;
            cpa16(&As[st][row][part*4], A + (size_t)(i0+row)*L + k0 + part*4);
        }
        #pragma unroll
        for (int it = 0; it < 4; it++) {
            int cid = tid + it*256;
            int row = cid >> 5, part = cid & 31;
            cpa16(&Bs[st][row][part*4], B + (size_t)(k0+row)*(L*DH) + nd0 + part*4);
        }
    };

    float acc[2][8][4];
    #pragma unroll
    for (int mt = 0; mt < 2; mt++)
        #pragma unroll
        for (int nt = 0; nt < 8; nt++)
            #pragma unroll
            for (int r = 0; r < 4; r++) acc[mt][nt][r] = 0.f;

    load(0, 0); CPA_COMMIT;
    for (int kt = 0; kt < 12; kt++) {
        CPA_WAIT0; __syncthreads();
        if (kt < 11) { load((kt+1)&1, (kt+1)*32); CPA_COMMIT; }
        int st = kt & 1;
        #pragma unroll
        for (int ks = 0; ks < 4; ks++) {
            int kk = ks*8;
            float a[2][4], b[8][2];
            #pragma unroll
            for (int mt = 0; mt < 2; mt++) {
                int mr = wm*32 + mt*16 + lrow;
                a[mt][0] = As[st][mr  ][kk+lq];
                a[mt][1] = As[st][mr+8][kk+lq];
                a[mt][2] = As[st][mr  ][kk+lq+4];
                a[mt][3] = As[st][mr+8][kk+lq+4];
            }
            #pragma unroll
            for (int nt = 0; nt < 8; nt++) {
                int nb = wn*64 + nt*8 + lrow;
                b[nt][0] = Bs[st][kk+lq  ][nb];
                b[nt][1] = Bs[st][kk+lq+4][nb];
            }
            #pragma unroll
            for (int mt = 0; mt < 2; mt++)
                #pragma unroll
                for (int nt = 0; nt < 8; nt++)
                    mma8(acc[mt][nt], a[mt], b[nt]);
        }
    }
    #pragma unroll
    for (int mt = 0; mt < 2; mt++)
        #pragma unroll
        for (int hf = 0; hf < 2; hf++) {
            int i = i0 + wm*32 + mt*16 + lrow + hf*8;
            #pragma unroll
            for (int nt = 0; nt < 8; nt++) {
                int nd = nd0 + wn*64 + nt*8 + 2*lq;
                int n = nd >> 5, d = nd & 31;
                size_t off = (size_t)(n*L + i)*DP + h*DH + d;
                float2 gv = *(const float2*)(g_gate + off);
                *(float2*)(g_o + off) =
                    make_float2(tf32r(acc[mt][nt][hf*2]  * gv.x),
                                tf32r(acc[mt][nt][hf*2+1]* gv.y));
            }
        }
}

// ---------------- kernel 7: out = g_o @ Wout + bout, 256 thr 2 CTA ----------------
__global__ __launch_bounds__(256, 2) void k_out(const float* __restrict__ bout,
                                                float* __restrict__ out)
{
    extern __shared__ float sm[];
    float (*As)[128][PADA] = (float(*)[128][PADA])sm;
    float (*Bs)[PADB]      = (float(*)[PADB])(sm + 2*128*PADA);
    int m0 = blockIdx.x * 128;
    int n  = m0 / L;
    int ib = m0 % L;
    int tid = threadIdx.x;
    int w = tid >> 5, lane = tid & 31;
    int wm = w >> 1, wn = w & 1;
    int lrow = lane >> 2, lq = lane & 3;

    auto loadA = [&](int st, int k0) {
        #pragma unroll
        for (int it = 0; it < 4; it++) {
            int cid = tid + it*256;
            int row = cid >> 3, part = cid & 7;
            cpa16(&As[st][row][part*4], g_o + (size_t)(m0+row)*DP + k0 + part*4);
        }
    };
    #pragma unroll
    for (int it = 0; it < 16; it++) {
        int cid = tid + it*256;
        int row = cid >> 5, part = cid & 31;
        cpa16(&Bs[row][part*4], g_wout + (size_t)row*DP + part*4);
    }
    loadA(0, 0); CPA_COMMIT;

    float acc[2][8][4];
    #pragma unroll
    for (int mt = 0; mt < 2; mt++)
        #pragma unroll
        for (int nt = 0; nt < 8; nt++)
            #pragma unroll
            for (int r = 0; r < 4; r++) acc[mt][nt][r] = 0.f;

    for (int kt = 0; kt < 4; kt++) {
        CPA_WAIT0; __syncthreads();
        if (kt < 3) { loadA((kt+1)&1, (kt+1)*32); CPA_COMMIT; }
        int st = kt & 1;
        #pragma unroll
        for (int ks = 0; ks < 4; ks++) {
            int kk = ks*8;
            float a[2][4], b[8][2];
            #pragma unroll
            for (int mt = 0; mt < 2; mt++) {
                int mr = wm*32 + mt*16 + lrow;
                a[mt][0] = As[st][mr  ][kk+lq];
                a[mt][1] = As[st][mr+8][kk+lq];
                a[mt][2] = As[st][mr  ][kk+lq+4];
                a[mt][3] = As[st][mr+8][kk+lq+4];
            }
            #pragma unroll
            for (int nt = 0; nt < 8; nt++) {
                int nb = wn*64 + nt*8 + lrow;
                b[nt][0] = Bs[kt*32+kk+lq  ][nb];
                b[nt][1] = Bs[kt*32+kk+lq+4][nb];
            }
            #pragma unroll
            for (int mt = 0; mt < 2; mt++)
                #pragma unroll
                for (int nt = 0; nt < 8; nt++)
                    mma8(acc[mt][nt], a[mt], b[nt]);
        }
    }
    #pragma unroll
    for (int mt = 0; mt < 2; mt++)
        #pragma unroll
        for (int hf = 0; hf < 2; hf++) {
            int i = ib + wm*32 + mt*16 + lrow + hf*8;
            size_t row = (size_t)i*L + n;
            #pragma unroll
            for (int nt = 0; nt < 8; nt++) {
                int c = wn*64 + nt*8 + 2*lq;
                *(float2*)(out + row*DP + c) =
                    make_float2(acc[mt][nt][hf*2]   + bout[c],
                                acc[mt][nt][hf*2+1] + bout[c+1]);
            }
        }
}

// ---------------- launch ----------------
extern "C" void kernel_launch(void* const* d_in, const int* in_sizes, int n_in,
                              void* d_out, int out_size)
{
    const float* pair    = (const float*)d_in[0];
    const float* bias    = (const float*)d_in[1];
    const float* gamma_p = (const float*)d_in[2];
    const float* beta_p  = (const float*)d_in[3];
    const float* gamma_b = (const float*)d_in[4];
    const float* beta_b  = (const float*)d_in[5];
    const float* Wq      = (const float*)d_in[6];
    const float* Wk      = (const float*)d_in[7];
    const float* Wv      = (const float*)d_in[8];
    const float* Wb      = (const float*)d_in[9];
    const float* Wg      = (const float*)d_in[10];
    const float* bg      = (const float*)d_in[11];
    const float* Wout    = (const float*)d_in[12];
    const float* bout    = (const float*)d_in[13];
    float* out = (float*)d_out;

    const int smProj = (128*APAD + 2*128*WPAD) * 4;      // 206848 B
    const int smQK   = 2 * (2*2*128*40) * 2;             // 81920 B
    const int smO    = (2*128*PADA + 2*32*PADB) * 4;     // 71680 B
    const int smOut  = (2*128*PADA + 128*PADB) * 4;      // 106496 B

    static cudaStream_t s1;
    static cudaEvent_t evFork, evJoin;
    static int inited = 0;
    if (!inited) {
        cudaFuncSetAttribute(k_projf, cudaFuncAttributeMaxDynamicSharedMemorySize, smProj);
        cudaFuncSetAttribute(k_qk,    cudaFuncAttributeMaxDynamicSharedMemorySize, smQK);
        cudaFuncSetAttribute(k_o,     cudaFuncAttributeMaxDynamicSharedMemorySize, smO);
        cudaFuncSetAttribute(k_out,   cudaFuncAttributeMaxDynamicSharedMemorySize, smOut);
        cudaStreamCreateWithFlags(&s1, cudaStreamNonBlocking);
        cudaEventCreateWithFlags(&evFork, cudaEventDisableTiming);
        cudaEventCreateWithFlags(&evJoin, cudaEventDisableTiming);
        inited = 1;
    }

    // fork: run k_bias concurrently with prep/projf/qk
    cudaEventRecord(evFork, 0);
    cudaStreamWaitEvent(s1, evFork, 0);
    k_bias    <<<LL/8, 256, 0, s1>>>(bias, gamma_b, beta_b, Wb);
    cudaEventRecord(evJoin, s1);

    k_prep    <<<320, 256>>>(Wq, Wk, Wv, Wg, Wout);
    k_projf   <<<LL/128, 512, smProj>>>(pair, gamma_p, beta_p, bg);
    k_qk      <<<dim3(3, 3, NH*SPLIT), 256, smQK>>>();

    cudaStreamWaitEvent(0, evJoin, 0);   // softmax needs battn
    k_softmax <<<dim3(L, NH), 128>>>();
    k_o       <<<dim3(3, (L*DH)/128, NH), 256, smO>>>();
    k_out     <<<LL/128, 256, smOut>>>(bout, out);
}